// round 1
// baseline (speedup 1.0000x reference)
#include <cuda_runtime.h>
#include <cuda_fp16.h>

#define BB 32
#define NR 36
#define DD 2048
#define CC 4
#define HH 512
#define H2 1024
#define NROWS (BB*NR)   // 1152

// Scratch (static device globals; no allocation APIs anywhere)
__device__ float  g_L[NROWS*H2];    // [cl | fl] per region-row, fp32
__device__ float  g_R[NROWS*H2];    // [cr | fr]
__device__ __half g_W[H2*DD];       // [k][d] fused output weights (W_cout ; W_fout), f16
__device__ __half g_Wff[DD*H2];     // [k][h] fused stage-1 weights (W_fl | W_fr), f16

// ---------------- prep kernels ----------------
__global__ void prep_w_out(const float* __restrict__ Wc, const float* __restrict__ Wf){
    int i = blockIdx.x*256 + threadIdx.x;
    if (i >= H2*DD) return;
    int k = i / DD;
    g_W[i] = __float2half(k < HH ? Wc[i] : Wf[i - HH*DD]);
}
__global__ void prep_w_in(const float* __restrict__ Wfl, const float* __restrict__ Wfr){
    int i = blockIdx.x*256 + threadIdx.x;
    if (i >= DD*H2) return;
    int k = i / H2, h = i - k*H2;
    g_Wff[i] = __float2half(h < HH ? Wfl[k*HH + h] : Wfr[k*HH + h - HH]);
}
__global__ void prep_coords(const float* __restrict__ coords,
                            const float* __restrict__ Wcl, const float* __restrict__ Wcr){
    int i = blockIdx.x*256 + threadIdx.x;
    if (i >= NROWS*HH) return;
    int row = i / HH, h = i - row*HH;
    const float* c = coords + row*CC;
    float al = 0.f, ar = 0.f;
#pragma unroll
    for (int q = 0; q < CC; q++){
        al = fmaf(c[q], Wcl[q*HH + h], al);
        ar = fmaf(c[q], Wcr[q*HH + h], ar);
    }
    g_L[row*H2 + h] = al;
    g_R[row*H2 + h] = ar;
}

// ---------------- mma helper (m16n8k16, f16 in / f32 acc) ----------------
__device__ __forceinline__ void mma16816(float c[4], const unsigned a[4], const unsigned b[2]){
    asm volatile("mma.sync.aligned.m16n8k16.row.col.f32.f16.f16.f32 "
                 "{%0,%1,%2,%3}, {%4,%5,%6,%7}, {%8,%9}, {%0,%1,%2,%3};\n"
                 : "+f"(c[0]), "+f"(c[1]), "+f"(c[2]), "+f"(c[3])
                 : "r"(a[0]), "r"(a[1]), "r"(a[2]), "r"(a[3]), "r"(b[0]), "r"(b[1]));
}

// ---------------- stage 1: [fl|fr] = mm @ [W_fl|W_fr]  (M=1152,K=2048,N=1024) ----------------
__global__ __launch_bounds__(256) void stage1_gemm(const float* __restrict__ mm){
    __shared__ __half As[128][36];   // BM=128 x KC=32, pad to 36 halves
    __shared__ __half Bs[64][36];    // BN=64 (n-major, k-contig)
    int tid = threadIdx.x, warp = tid>>5, lane = tid&31;
    int m0 = blockIdx.y*128, n0 = blockIdx.x*64;
    int wm = (warp>>1)*32, wn = (warp&1)*32;
    float acc[2][4][4];
#pragma unroll
    for (int a=0;a<2;a++) for (int b=0;b<4;b++) for (int c=0;c<4;c++) acc[a][b][c]=0.f;

    for (int k0 = 0; k0 < DD; k0 += 32){
        { // A tile: 128x32 floats -> f16
            int r = tid>>1, kq = (tid&1)*16;
            const float4* p = reinterpret_cast<const float4*>(mm + (m0+r)*DD + k0 + kq);
#pragma unroll
            for (int q=0;q<4;q++){
                float4 v = p[q];
                int k = kq + q*4;
                *reinterpret_cast<__half2*>(&As[r][k])   = __floats2half2_rn(v.x, v.y);
                *reinterpret_cast<__half2*>(&As[r][k+2]) = __floats2half2_rn(v.z, v.w);
            }
        }
        { // B tile: 32k x 64n from g_Wff, stored transposed [n][k]
            int n = (tid & 7)*8, k = tid>>3;
            uint4 d = *reinterpret_cast<const uint4*>(&g_Wff[(k0+k)*H2 + n0 + n]);
            const __half* h = reinterpret_cast<const __half*>(&d);
#pragma unroll
            for (int e=0;e<8;e++) Bs[n+e][k] = h[e];
        }
        __syncthreads();
#pragma unroll
        for (int ks=0; ks<2; ks++){
            int kk = ks*16 + (lane&3)*2;
            unsigned bf[4][2];
#pragma unroll
            for (int nf=0;nf<4;nf++){
                int n = wn + nf*8 + (lane>>2);
                bf[nf][0] = *reinterpret_cast<const unsigned*>(&Bs[n][kk]);
                bf[nf][1] = *reinterpret_cast<const unsigned*>(&Bs[n][kk+8]);
            }
#pragma unroll
            for (int mf=0;mf<2;mf++){
                int r = wm + mf*16 + (lane>>2);
                unsigned af[4];
                af[0] = *reinterpret_cast<const unsigned*>(&As[r][kk]);
                af[1] = *reinterpret_cast<const unsigned*>(&As[r+8][kk]);
                af[2] = *reinterpret_cast<const unsigned*>(&As[r][kk+8]);
                af[3] = *reinterpret_cast<const unsigned*>(&As[r+8][kk+8]);
#pragma unroll
                for (int nf=0;nf<4;nf++) mma16816(acc[mf][nf], af, bf[nf]);
            }
        }
        __syncthreads();
    }
    // epilogue: col<512 -> fl -> g_L[row][512+col]; col>=512 -> fr -> g_R[row][col]
#pragma unroll
    for (int mf=0;mf<2;mf++){
#pragma unroll
        for (int nf=0;nf<4;nf++){
            int r   = m0 + wm + mf*16 + (lane>>2);
            int col = n0 + wn + nf*8 + (lane&3)*2;
#pragma unroll
            for (int hi=0;hi<2;hi++){
#pragma unroll
                for (int j=0;j<2;j++){
                    int rr = r + hi*8, cc = col + j;
                    float v = acc[mf][nf][hi*2+j];
                    if (cc < HH) g_L[rr*H2 + HH + cc] = v;
                    else         g_R[rr*H2 + cc]      = v;
                }
            }
        }
    }
}

// ---------------- main fused pair-GEMM + segmented max + residual ----------------
// CTA: (n-tile of 128 d-cols) x (i-group of 4) x (batch). BM = 4*36 = 144 rows (no padding).
__global__ __launch_bounds__(256) void pair_gemm(const float* __restrict__ mm, float* __restrict__ out){
    __shared__ __half As[144][36];
    __shared__ __half Bs[128][36];
    __shared__ float  Ls[4][32];
    __shared__ float  Rs[36][32];
    int tid = threadIdx.x, warp = tid>>5, lane = tid&31;
    int b = blockIdx.z, ig = blockIdx.y, n0 = blockIdx.x*128;
    const float* Lb = g_L + (b*NR + ig*4)*H2;
    const float* Rb = g_R + (b*NR)*H2;
    float acc[9][2][4];
#pragma unroll
    for (int m=0;m<9;m++) for (int n=0;n<2;n++) for (int c=0;c<4;c++) acc[m][n][c]=0.f;

    for (int k0 = 0; k0 < H2; k0 += 32){
        // stage L (4 rows) and R (36 rows) chunks: 1280 floats, 5 per thread
#pragma unroll
        for (int q=0;q<5;q++){
            int idx = tid + q*256;
            if (idx < 1152){ int j = idx>>5, k = idx&31; Rs[j][k] = Rb[j*H2 + k0 + k]; }
            else { int e = idx - 1152; int gg = e>>5, k = e&31; Ls[gg][k] = Lb[gg*H2 + k0 + k]; }
        }
        // B tile: 32k x 128n from g_W (f16), stored transposed [n][k]
#pragma unroll
        for (int q=0;q<2;q++){
            int v = tid + q*256;                 // 512 vectors of 8 halves
            int n = (v & 15)*8, k = v>>4;
            uint4 d = *reinterpret_cast<const uint4*>(&g_W[(k0+k)*DD + n0 + n]);
            const __half* h = reinterpret_cast<const __half*>(&d);
#pragma unroll
            for (int e=0;e<8;e++) Bs[n+e][k] = h[e];
        }
        __syncthreads();
        // produce A = l_g ⊙ r_j on the fly: 144x32 halves (half2 stores)
#pragma unroll
        for (int q=0;q<9;q++){
            int idx = tid + q*256;               // 0..2303 half2 elements
            int row = idx>>4, k2 = (idx&15)*2;
            int gg = row/36, j = row - gg*36;
            *reinterpret_cast<__half2*>(&As[row][k2]) =
                __floats2half2_rn(Ls[gg][k2]*Rs[j][k2], Ls[gg][k2+1]*Rs[j][k2+1]);
        }
        __syncthreads();
#pragma unroll
        for (int ks=0; ks<2; ks++){
            int kk = ks*16 + (lane&3)*2;
            unsigned bf[2][2];
#pragma unroll
            for (int nf=0;nf<2;nf++){
                int n = warp*16 + nf*8 + (lane>>2);
                bf[nf][0] = *reinterpret_cast<const unsigned*>(&Bs[n][kk]);
                bf[nf][1] = *reinterpret_cast<const unsigned*>(&Bs[n][kk+8]);
            }
#pragma unroll
            for (int mf=0;mf<9;mf++){
                int r = mf*16 + (lane>>2);
                unsigned af[4];
                af[0] = *reinterpret_cast<const unsigned*>(&As[r][kk]);
                af[1] = *reinterpret_cast<const unsigned*>(&As[r+8][kk]);
                af[2] = *reinterpret_cast<const unsigned*>(&As[r][kk+8]);
                af[3] = *reinterpret_cast<const unsigned*>(&As[r+8][kk+8]);
                mma16816(acc[mf][0], af, bf[0]);
                mma16816(acc[mf][1], af, bf[1]);
            }
        }
        __syncthreads();
    }

    // Epilogue: segmented max over each 36-row group (j axis), + residual, write out.
    int r0 = lane>>2, cq = lane&3;
#pragma unroll
    for (int g=0; g<4; g++){
        float mx[2][2] = {{-1e30f,-1e30f},{-1e30f,-1e30f}};
#pragma unroll
        for (int s=0; s<18; s++){
            int row = r0 + 8*s;                  // this thread's accumulated rows
            if (row >= g*36 && row < g*36 + 36){
                int mf = s>>1, hi = s&1;
#pragma unroll
                for (int nf=0;nf<2;nf++){
                    mx[nf][0] = fmaxf(mx[nf][0], acc[mf][nf][hi*2]);
                    mx[nf][1] = fmaxf(mx[nf][1], acc[mf][nf][hi*2+1]);
                }
            }
        }
#pragma unroll
        for (int off=4; off<32; off<<=1){
#pragma unroll
            for (int nf=0;nf<2;nf++){
                mx[nf][0] = fmaxf(mx[nf][0], __shfl_xor_sync(0xffffffffu, mx[nf][0], off));
                mx[nf][1] = fmaxf(mx[nf][1], __shfl_xor_sync(0xffffffffu, mx[nf][1], off));
            }
        }
        if (r0 == g){
            int base = (b*NR + ig*4 + g)*DD;
#pragma unroll
            for (int nf=0;nf<2;nf++){
#pragma unroll
                for (int j=0;j<2;j++){
                    int col = n0 + warp*16 + nf*8 + cq*2 + j;
                    out[base + col] = mx[nf][j] + mm[base + col];
                }
            }
        }
    }
}

// ---------------- launch ----------------
extern "C" void kernel_launch(void* const* d_in, const int* in_sizes, int n_in,
                              void* d_out, int out_size){
    (void)in_sizes; (void)n_in; (void)out_size;
    const float* mm     = (const float*)d_in[0];
    const float* coords = (const float*)d_in[1];
    const float* W_cl   = (const float*)d_in[2];
    const float* W_cr   = (const float*)d_in[3];
    const float* W_cout = (const float*)d_in[4];
    const float* W_fl   = (const float*)d_in[5];
    const float* W_fr   = (const float*)d_in[6];
    const float* W_fout = (const float*)d_in[7];
    float* out = (float*)d_out;

    prep_w_out  <<<(H2*DD + 255)/256, 256>>>(W_cout, W_fout);
    prep_w_in   <<<(DD*H2 + 255)/256, 256>>>(W_fl, W_fr);
    prep_coords <<<(NROWS*HH + 255)/256, 256>>>(coords, W_cl, W_cr);
    stage1_gemm <<<dim3(H2/64, NROWS/128), 256>>>(mm);
    pair_gemm   <<<dim3(DD/128, NR/4, BB), 256>>>(mm, out);
}

// round 5
// speedup vs baseline: 1.3467x; 1.3467x over previous
#include <cuda_runtime.h>
#include <cuda_fp16.h>
#include <cstdint>

#define BB 32
#define NR 36
#define DD 2048
#define CC 4
#define HH 512
#define H2 1024
#define NROWS (BB*NR)   // 1152

// Scratch (static device globals)
__device__ float  g_L [NROWS*H2];   // [cl | fl] fp32
__device__ __half g_Rh[NROWS*H2];   // [cr | fr] fp16
__device__ __half g_Wt[DD*H2];      // W^T: [d][k] fp16 (W_cout;W_fout fused on k)
__device__ __half g_Wff[DD*H2];     // [k][h] fused stage-1 weights (W_fl | W_fr)

// ---------------- helpers ----------------
__device__ __forceinline__ uint32_t sm_u32(const void* p){
    uint32_t a;
    asm("{ .reg .u64 t; cvta.to.shared.u64 t, %1; cvt.u32.u64 %0, t; }" : "=r"(a) : "l"(p));
    return a;
}
__device__ __forceinline__ void mma16816(float c[4], const uint32_t a[4], const uint32_t b0, const uint32_t b1){
    asm volatile("mma.sync.aligned.m16n8k16.row.col.f32.f16.f16.f32 "
                 "{%0,%1,%2,%3}, {%4,%5,%6,%7}, {%8,%9}, {%0,%1,%2,%3};\n"
                 : "+f"(c[0]), "+f"(c[1]), "+f"(c[2]), "+f"(c[3])
                 : "r"(a[0]), "r"(a[1]), "r"(a[2]), "r"(a[3]), "r"(b0), "r"(b1));
}
__device__ __forceinline__ void ldm_x4(uint32_t d[4], uint32_t addr){
    asm volatile("ldmatrix.sync.aligned.m8n8.x4.shared.b16 {%0,%1,%2,%3}, [%4];"
                 : "=r"(d[0]), "=r"(d[1]), "=r"(d[2]), "=r"(d[3]) : "r"(addr));
}
__device__ __forceinline__ void cpa16(uint32_t dst, const void* src){
    asm volatile("cp.async.cg.shared.global [%0], [%1], 16;"
                 :: "r"(dst), "l"(__cvta_generic_to_global(src)) : "memory");
}
__device__ __forceinline__ void cpa_commit(){ asm volatile("cp.async.commit_group;" ::: "memory"); }
__device__ __forceinline__ void cpa_wait0(){ asm volatile("cp.async.wait_group 0;" ::: "memory"); }
__device__ __forceinline__ unsigned f2mono(float v){
    unsigned b = __float_as_uint(v);
    return (b & 0x80000000u) ? ~b : (b | 0x80000000u);
}
__device__ __forceinline__ float mono2f(unsigned u){
    return (u & 0x80000000u) ? __uint_as_float(u ^ 0x80000000u) : __uint_as_float(~u);
}

// ---------------- prep kernels ----------------
__global__ void prep_w_out_t(const float* __restrict__ Wc, const float* __restrict__ Wf){
    __shared__ float ts[64][33];
    int tid = threadIdx.x;
    int d0 = blockIdx.x*64, k0 = blockIdx.y*32;
#pragma unroll
    for (int q=0;q<8;q++){
        int idx = tid + 256*q;
        int kk = idx>>6, dd = idx&63;
        int k = k0 + kk;
        float v = (k < HH) ? Wc[k*DD + d0 + dd] : Wf[(k-HH)*DD + d0 + dd];
        ts[dd][kk] = v;
    }
    __syncthreads();
    __half2* Wt2 = reinterpret_cast<__half2*>(g_Wt);
#pragma unroll
    for (int q=0;q<4;q++){
        int idx = tid + 256*q;
        int dd = idx>>4, kk2 = idx&15;
        Wt2[(d0+dd)*(H2/2) + (k0>>1) + kk2] =
            __floats2half2_rn(ts[dd][kk2*2], ts[dd][kk2*2+1]);
    }
}
__global__ void prep_w_in(const float* __restrict__ Wfl, const float* __restrict__ Wfr){
    int i = blockIdx.x*256 + threadIdx.x;
    if (i >= DD*H2) return;
    int k = i / H2, h = i - k*H2;
    g_Wff[i] = __float2half(h < HH ? Wfl[k*HH + h] : Wfr[k*HH + h - HH]);
}
__global__ void prep_coords(const float* __restrict__ coords,
                            const float* __restrict__ Wcl, const float* __restrict__ Wcr){
    int i = blockIdx.x*256 + threadIdx.x;
    if (i >= NROWS*HH) return;
    int row = i / HH, h = i - row*HH;
    const float* c = coords + row*CC;
    float al = 0.f, ar = 0.f;
#pragma unroll
    for (int q = 0; q < CC; q++){
        al = fmaf(c[q], Wcl[q*HH + h], al);
        ar = fmaf(c[q], Wcr[q*HH + h], ar);
    }
    g_L [row*H2 + h] = al;
    g_Rh[row*H2 + h] = __float2half(ar);
}

// ---------------- stage 1: [fl|fr] = mm @ [W_fl|W_fr] (M=1152,K=2048,N=1024) ----------------
__global__ __launch_bounds__(256) void stage1_gemm(const float* __restrict__ mm){
    __shared__ __half As[64][36];
    __shared__ __half Bs[64][36];
    int tid = threadIdx.x, warp = tid>>5, lane = tid&31;
    int m0 = blockIdx.y*64, n0 = blockIdx.x*64;
    int wm = (warp&3)*16, wn = (warp>>2)*32;
    float acc[4][4];
#pragma unroll
    for (int b=0;b<4;b++) for (int c=0;c<4;c++) acc[b][c]=0.f;

    for (int k0 = 0; k0 < DD; k0 += 32){
        { // A tile: 64x32 floats -> f16
            int r = tid>>2, kq = (tid&3)*8;
            const float4* p = reinterpret_cast<const float4*>(mm + (size_t)(m0+r)*DD + k0 + kq);
#pragma unroll
            for (int q=0;q<2;q++){
                float4 v = p[q];
                int k = kq + q*4;
                *reinterpret_cast<__half2*>(&As[r][k])   = __floats2half2_rn(v.x, v.y);
                *reinterpret_cast<__half2*>(&As[r][k+2]) = __floats2half2_rn(v.z, v.w);
            }
        }
        { // B tile: 32k x 64n transposed [n][k]
            int n = (tid & 7)*8, k = tid>>3;
            uint4 d = *reinterpret_cast<const uint4*>(&g_Wff[(size_t)(k0+k)*H2 + n0 + n]);
            const __half* h = reinterpret_cast<const __half*>(&d);
#pragma unroll
            for (int e=0;e<8;e++) Bs[n+e][k] = h[e];
        }
        __syncthreads();
#pragma unroll
        for (int ks=0; ks<2; ks++){
            int kk = ks*16 + (lane&3)*2;
            uint32_t bf[4][2];
#pragma unroll
            for (int nf=0;nf<4;nf++){
                int n = wn + nf*8 + (lane>>2);
                bf[nf][0] = *reinterpret_cast<const uint32_t*>(&Bs[n][kk]);
                bf[nf][1] = *reinterpret_cast<const uint32_t*>(&Bs[n][kk+8]);
            }
            int r = wm + (lane>>2);
            uint32_t af[4];
            af[0] = *reinterpret_cast<const uint32_t*>(&As[r][kk]);
            af[1] = *reinterpret_cast<const uint32_t*>(&As[r+8][kk]);
            af[2] = *reinterpret_cast<const uint32_t*>(&As[r][kk+8]);
            af[3] = *reinterpret_cast<const uint32_t*>(&As[r+8][kk+8]);
#pragma unroll
            for (int nf=0;nf<4;nf++) mma16816(acc[nf], af, bf[nf][0], bf[nf][1]);
        }
        __syncthreads();
    }
#pragma unroll
    for (int nf=0;nf<4;nf++){
        int r   = m0 + wm + (lane>>2);
        int col = n0 + wn + nf*8 + (lane&3)*2;
#pragma unroll
        for (int hi=0;hi<2;hi++){
#pragma unroll
            for (int j=0;j<2;j++){
                int rr = r + hi*8, cc = col + j;
                float v = acc[nf][hi*2+j];
                if (cc < HH) g_L[(size_t)rr*H2 + HH + cc] = v;
                else         g_Rh[(size_t)rr*H2 + cc]    = __float2half(v);
            }
        }
    }
}

// ---------------- pair GEMM: mma.sync + ldmatrix + cp.async double buffer ----------------
// BM=144 pair-rows (4 i-groups x 36 j), BN=128 d-cols, BK=32, 384 threads (3m x 4n warps)
#define SM_LS 0                       // 4 rows x 1024 fp32 = 16384
#define SM_A0 16384                   // 144 x 40 halves (80B stride) = 11520
#define SM_A1 27904
#define SM_B0 39424                   // 128 x 40 halves = 10240
#define SM_B1 49664
#define SM_R0 59904                   // 36 rows x 32 halves = 2304
#define SM_R1 62208
#define SM_TOT 64512

__device__ __forceinline__ void issue_loads(uint32_t smb, int t, int sel, int tid, int n0, int rbase){
    // B tile: 128 rows x 64B from g_Wt (row-major d, k contig)
    uint32_t bdst = smb + (sel ? SM_B1 : SM_B0);
    const char* bsrc = (const char*)g_Wt + (size_t)n0*2048 + (size_t)t*64;
    {
        int p = tid;
        cpa16(bdst + (p>>2)*80 + (p&3)*16, bsrc + (size_t)(p>>2)*2048 + (p&3)*16);
        if (tid < 128){
            int p2 = tid + 384;
            cpa16(bdst + (p2>>2)*80 + (p2&3)*16, bsrc + (size_t)(p2>>2)*2048 + (p2&3)*16);
        }
    }
    // R tile: 36 rows x 64B from g_Rh
    if (tid < 144){
        uint32_t rdst = smb + (sel ? SM_R1 : SM_R0) + (tid>>2)*64 + (tid&3)*16;
        const char* rsrc = (const char*)g_Rh + (size_t)(rbase + (tid>>2))*2048 + (size_t)t*64 + (tid&3)*16;
        cpa16(rdst, rsrc);
    }
    cpa_commit();
}

__device__ __forceinline__ void build_A(char* sm, int t, int sel, int tid,
                                        const int* ggq, const int* jq){
    const float2*  Ls2 = (const float2*)(sm + SM_LS);
    const __half2* Rs2 = (const __half2*)(sm + (sel ? SM_R1 : SM_R0));
    char* Ab = sm + (sel ? SM_A1 : SM_A0);
    int k2 = tid & 15;
#pragma unroll
    for (int q=0;q<6;q++){
        int row = (tid>>4) + 24*q;
        float2 l = Ls2[ggq[q]*512 + t*16 + k2];
        float2 r = __half22float2(Rs2[jq[q]*16 + k2]);
        *reinterpret_cast<__half2*>(Ab + row*80 + k2*4) =
            __floats2half2_rn(l.x*r.x, l.y*r.y);
    }
}

__global__ void __launch_bounds__(384) pair_gemm(const float* __restrict__ mm, float* __restrict__ out){
    extern __shared__ char sm[];
    const int tid = threadIdx.x, w = tid>>5, lane = tid&31;
    const int n0 = blockIdx.x*128;
    const int by = blockIdx.y, b = by/9, ig = by - b*9;
    const int lrow0 = b*NR + ig*4, rbase = b*NR;
    const uint32_t smb = sm_u32(sm);
    const int mrow0 = (w % 3)*48, ncol0 = (w / 3)*32;

    // precompute builder row decomposition (constant across chunks)
    int ggq[6], jq[6];
#pragma unroll
    for (int q=0;q<6;q++){
        int row = (tid>>4) + 24*q;
        ggq[q] = row/36; jq[q] = row - 36*ggq[q];
    }

    // load L: 4 rows x 1024 fp32
    {
        const float4* src = reinterpret_cast<const float4*>(g_L + (size_t)lrow0*H2);
        float4* dst = reinterpret_cast<float4*>(sm + SM_LS);
#pragma unroll
        for (int q=0;q<3;q++){
            int idx = tid + 384*q;
            if (idx < 1024) dst[idx] = src[idx];
        }
    }

    float acc[3][4][4];
#pragma unroll
    for (int m=0;m<3;m++) for (int n=0;n<4;n++) for (int c=0;c<4;c++) acc[m][n][c]=0.f;

    // prologue
    issue_loads(smb, 0, 0, tid, n0, rbase);
    cpa_wait0();
    __syncthreads();
    build_A(sm, 0, 0, tid, ggq, jq);
    __syncthreads();

    for (int t=0; t<32; t++){
        const int sel = t & 1, nsel = sel ^ 1;
        if (t < 31) issue_loads(smb, t+1, nsel, tid, n0, rbase);

        // compute chunk t
        const uint32_t ab = smb + (sel ? SM_A1 : SM_A0);
        const uint32_t bb = smb + (sel ? SM_B1 : SM_B0);
#pragma unroll
        for (int ks=0; ks<2; ks++){
            uint32_t a[3][4];
#pragma unroll
            for (int mf=0;mf<3;mf++){
                uint32_t ad = ab + (uint32_t)(mrow0 + mf*16 + (lane&15))*80
                            + (uint32_t)(ks*16 + ((lane>>4)<<3))*2;
                ldm_x4(a[mf], ad);
            }
            uint32_t bf[2][4];
#pragma unroll
            for (int g=0; g<2; g++){
                uint32_t bd = bb + (uint32_t)(ncol0 + g*16 + (lane&15))*80
                            + (uint32_t)(ks*32 + ((lane>>4)<<4));
                ldm_x4(bf[g], bd);
            }
#pragma unroll
            for (int mf=0;mf<3;mf++){
#pragma unroll
                for (int nf=0;nf<4;nf++){
                    int g = nf>>1, hi = nf&1;
                    mma16816(acc[mf][nf], a[mf], bf[g][hi], bf[g][hi+2]);
                }
            }
        }

        cpa_wait0();
        __syncthreads();
        if (t < 31) build_A(sm, t+1, nsel, tid, ggq, jq);
        __syncthreads();
    }

    // epilogue: segmented max over j (36-row groups) via smem atomicMax on monotone encoding
    unsigned* redu = reinterpret_cast<unsigned*>(sm);   // 512 entries (reuses Ls space)
    redu[tid] = 0u;
    if (tid < 128) redu[tid+384] = 0u;
    __syncthreads();
#pragma unroll
    for (int mf=0;mf<3;mf++){
#pragma unroll
        for (int hi=0;hi<2;hi++){
            int row = mrow0 + mf*16 + hi*8 + (lane>>2);
            int gg = row/36;
#pragma unroll
            for (int nf=0;nf<4;nf++){
#pragma unroll
                for (int cj=0;cj<2;cj++){
                    int col = ncol0 + nf*8 + (lane&3)*2 + cj;
                    atomicMax(&redu[gg*128 + col], f2mono(acc[mf][nf][hi*2+cj]));
                }
            }
        }
    }
    __syncthreads();
    for (int idx = tid; idx < 512; idx += 384){
        int gg = idx>>7, col = idx&127;
        float v = mono2f(redu[idx]);
        size_t o = (size_t)(lrow0 + gg)*DD + n0 + col;
        out[o] = v + mm[o];
    }
}

// ---------------- launch ----------------
extern "C" void kernel_launch(void* const* d_in, const int* in_sizes, int n_in,
                              void* d_out, int out_size){
    (void)in_sizes; (void)n_in; (void)out_size;
    const float* mm     = (const float*)d_in[0];
    const float* coords = (const float*)d_in[1];
    const float* W_cl   = (const float*)d_in[2];
    const float* W_cr   = (const float*)d_in[3];
    const float* W_cout = (const float*)d_in[4];
    const float* W_fl   = (const float*)d_in[5];
    const float* W_fr   = (const float*)d_in[6];
    const float* W_fout = (const float*)d_in[7];
    float* out = (float*)d_out;

    cudaFuncSetAttribute(pair_gemm, cudaFuncAttributeMaxDynamicSharedMemorySize, SM_TOT);

    prep_w_out_t<<<dim3(32,32), 256>>>(W_cout, W_fout);
    prep_w_in   <<<(DD*H2 + 255)/256, 256>>>(W_fl, W_fr);
    prep_coords <<<(NROWS*HH + 255)/256, 256>>>(coords, W_cl, W_cr);
    stage1_gemm <<<dim3(16,18), 256>>>(mm);
    pair_gemm   <<<dim3(16,288), 384, SM_TOT>>>(mm, out);
}

// round 6
// speedup vs baseline: 3.6154x; 2.6847x over previous
#include <cuda_runtime.h>
#include <cuda_fp16.h>
#include <cstdint>

#define BB 32
#define NR 36
#define DD 2048
#define CC 4
#define HH 512
#define HF 512
#define NROWS (BB*NR)   // 1152

// Scratch (static device globals)
__device__ __half g_mmh [NROWS*DD];   // mm in f16
__device__ __half g_Lh  [NROWS*HF];   // fl f16
__device__ __half g_Rh  [NROWS*HF];   // fr f16
__device__ __half g_Wt  [DD*HF];      // W_fout^T: [d][k]
__device__ __half g_WffT[1024*DD];    // [h][k] fused (W_fl|W_fr) transposed
__device__ __half g_T   [DD*16];      // coord tensor T[d][p*4+q] * 64

// ---------------- helpers ----------------
__device__ __forceinline__ uint32_t sm_u32(const void* p){
    uint32_t a;
    asm("{ .reg .u64 t; cvta.to.shared.u64 t, %1; cvt.u32.u64 %0, t; }" : "=r"(a) : "l"(p));
    return a;
}
__device__ __forceinline__ void mma16816(float c[4], const uint32_t a[4], const uint32_t b0, const uint32_t b1){
    asm volatile("mma.sync.aligned.m16n8k16.row.col.f32.f16.f16.f32 "
                 "{%0,%1,%2,%3}, {%4,%5,%6,%7}, {%8,%9}, {%0,%1,%2,%3};\n"
                 : "+f"(c[0]), "+f"(c[1]), "+f"(c[2]), "+f"(c[3])
                 : "r"(a[0]), "r"(a[1]), "r"(a[2]), "r"(a[3]), "r"(b0), "r"(b1));
}
__device__ __forceinline__ void ldm_x4(uint32_t d[4], uint32_t addr){
    asm volatile("ldmatrix.sync.aligned.m8n8.x4.shared.b16 {%0,%1,%2,%3}, [%4];"
                 : "=r"(d[0]), "=r"(d[1]), "=r"(d[2]), "=r"(d[3]) : "r"(addr));
}
__device__ __forceinline__ void cpa16(uint32_t dst, const void* src){
    asm volatile("cp.async.cg.shared.global [%0], [%1], 16;"
                 :: "r"(dst), "l"(__cvta_generic_to_global(src)) : "memory");
}
__device__ __forceinline__ void cpa_commit(){ asm volatile("cp.async.commit_group;" ::: "memory"); }
__device__ __forceinline__ void cpa_wait0(){ asm volatile("cp.async.wait_group 0;" ::: "memory"); }
__device__ __forceinline__ void cpa_wait1(){ asm volatile("cp.async.wait_group 1;" ::: "memory"); }
__device__ __forceinline__ unsigned f2mono(float v){
    unsigned b = __float_as_uint(v);
    return (b & 0x80000000u) ? ~b : (b | 0x80000000u);
}
__device__ __forceinline__ float mono2f(unsigned u){
    return (u & 0x80000000u) ? __uint_as_float(u ^ 0x80000000u) : __uint_as_float(~u);
}

// ---------------- prep kernels ----------------
__global__ void prep_mmh(const float* __restrict__ mm){
    int i = blockIdx.x*256 + threadIdx.x;        // 294912 total
    const float4* s = reinterpret_cast<const float4*>(mm);
    float4 v0 = s[i*2], v1 = s[i*2+1];
    __half2* d = reinterpret_cast<__half2*>(g_mmh) + i*4;
    d[0] = __floats2half2_rn(v0.x, v0.y);
    d[1] = __floats2half2_rn(v0.z, v0.w);
    d[2] = __floats2half2_rn(v1.x, v1.y);
    d[3] = __floats2half2_rn(v1.z, v1.w);
}
// W_fout [512][2048] -> g_Wt [2048][512]
__global__ void prep_w_out_t(const float* __restrict__ Wf){
    __shared__ float ts[64][33];
    int tid = threadIdx.x;
    int d0 = blockIdx.x*64, k0 = blockIdx.y*32;
#pragma unroll
    for (int q=0;q<8;q++){
        int idx = tid + 256*q;
        int kk = idx>>6, dd = idx&63;
        ts[dd][kk] = Wf[(size_t)(k0+kk)*DD + d0 + dd];
    }
    __syncthreads();
    __half2* Wt2 = reinterpret_cast<__half2*>(g_Wt);
#pragma unroll
    for (int q=0;q<4;q++){
        int idx = tid + 256*q;
        int dd = idx>>4, kk2 = idx&15;
        Wt2[(size_t)(d0+dd)*(HF/2) + (k0>>1) + kk2] =
            __floats2half2_rn(ts[dd][kk2*2], ts[dd][kk2*2+1]);
    }
}
// (W_fl|W_fr) [2048][1024] -> g_WffT [1024][2048]
__global__ void prep_w_in_t(const float* __restrict__ Wfl, const float* __restrict__ Wfr){
    __shared__ float ts[64][33];
    int tid = threadIdx.x;
    int h0 = blockIdx.x*64, k0 = blockIdx.y*32;
#pragma unroll
    for (int q=0;q<8;q++){
        int idx = tid + 256*q;
        int kk = idx>>6, hh = idx&63;
        int h = h0 + hh, k = k0 + kk;
        ts[hh][kk] = (h < HH) ? Wfl[(size_t)k*HH + h] : Wfr[(size_t)k*HH + h - HH];
    }
    __syncthreads();
    __half2* W2 = reinterpret_cast<__half2*>(g_WffT);
#pragma unroll
    for (int q=0;q<4;q++){
        int idx = tid + 256*q;
        int hh = idx>>4, kk2 = idx&15;
        W2[(size_t)(h0+hh)*(DD/2) + (k0>>1) + kk2] =
            __floats2half2_rn(ts[hh][kk2*2], ts[hh][kk2*2+1]);
    }
}
// T[d][p*4+q] = 64 * sum_h Wcl[p][h]*Wcr[q][h]*Wcout[h][d]
__global__ void prep_T(const float* __restrict__ Wcl, const float* __restrict__ Wcr,
                       const float* __restrict__ Wc){
    __shared__ float scl[4][512], scr[4][512];
    int tid = threadIdx.x;                      // 128 threads
    for (int i = tid; i < 4*512; i += 128){
        scl[i>>9][i&511] = Wcl[i];
        scr[i>>9][i&511] = Wcr[i];
    }
    __syncthreads();
    int d = blockIdx.x*128 + tid;
    float acc[16];
#pragma unroll
    for (int e=0;e<16;e++) acc[e]=0.f;
    for (int h=0; h<512; h++){
        float wc = Wc[(size_t)h*DD + d];
#pragma unroll
        for (int p=0;p<4;p++){
            float a = scl[p][h]*wc;
#pragma unroll
            for (int q=0;q<4;q++) acc[p*4+q] = fmaf(a, scr[q][h], acc[p*4+q]);
        }
    }
#pragma unroll
    for (int e=0;e<16;e++) g_T[d*16+e] = __float2half(acc[e]*64.0f);
}

// ---------------- stage 1: [fl|fr] = mm @ [W_fl|W_fr] (M=1152,K=2048,N=1024) ----------------
// BM=64, BN=64, BK=32, 128 threads (2m x 2n warps), cp.async double buffer + ldmatrix
#define S1_A0 0
#define S1_A1 5120
#define S1_B0 10240
#define S1_B1 15360

__device__ __forceinline__ void s1_issue(uint32_t smb, int t, int sel, int tid, int m0, int n0){
    uint32_t Ab = smb + (sel ? S1_A1 : S1_A0);
    uint32_t Bb = smb + (sel ? S1_B1 : S1_B0);
#pragma unroll
    for (int q=0;q<2;q++){
        int idx = tid + 128*q, row = idx>>2, seg = idx&3;
        cpa16(Ab + row*80 + seg*16, (const char*)g_mmh  + (size_t)(m0+row)*4096 + t*64 + seg*16);
        cpa16(Bb + row*80 + seg*16, (const char*)g_WffT + (size_t)(n0+row)*4096 + t*64 + seg*16);
    }
    cpa_commit();
}

__global__ __launch_bounds__(128) void stage1_gemm(){
    __shared__ char sm[20480];
    uint32_t smb = sm_u32(sm);
    int tid = threadIdx.x, warp = tid>>5, lane = tid&31;
    int n0 = blockIdx.x*64, m0 = blockIdx.y*64;
    int wm = (warp&1)*32, wn = (warp>>1)*32;
    float acc[2][4][4];
#pragma unroll
    for (int a=0;a<2;a++) for (int b=0;b<4;b++) for (int c=0;c<4;c++) acc[a][b][c]=0.f;

    s1_issue(smb, 0, 0, tid, m0, n0);
    for (int t=0; t<64; t++){
        int sel = t&1;
        if (t<63){ s1_issue(smb, t+1, sel^1, tid, m0, n0); cpa_wait1(); }
        else cpa_wait0();
        __syncthreads();
        uint32_t Ab = smb + (sel ? S1_A1 : S1_A0);
        uint32_t Bb = smb + (sel ? S1_B1 : S1_B0);
#pragma unroll
        for (int ks=0; ks<2; ks++){
            uint32_t a[2][4], bfr[2][4];
#pragma unroll
            for (int mf=0;mf<2;mf++)
                ldm_x4(a[mf], Ab + (uint32_t)(wm+mf*16+(lane&15))*80 + ks*32 + ((lane>>4)<<4));
#pragma unroll
            for (int g=0;g<2;g++)
                ldm_x4(bfr[g], Bb + (uint32_t)(wn+g*16+(lane&15))*80 + ks*32 + ((lane>>4)<<4));
#pragma unroll
            for (int mf=0;mf<2;mf++)
#pragma unroll
                for (int g=0;g<2;g++)
#pragma unroll
                    for (int hi=0;hi<2;hi++)
                        mma16816(acc[mf][g*2+hi], a[mf], bfr[g][hi], bfr[g][hi+2]);
        }
        __syncthreads();
    }
#pragma unroll
    for (int mf=0;mf<2;mf++)
#pragma unroll
        for (int nf=0;nf<4;nf++){
            int g = nf>>1, hi = nf&1;
#pragma unroll
            for (int ci=0;ci<4;ci++){
                int row = m0 + wm + mf*16 + (lane>>2) + (ci>>1)*8;
                int col = n0 + wn + g*16 + hi*8 + (lane&3)*2 + (ci&1);
                __half v = __float2half(acc[mf][nf][ci]);
                if (col < HH) g_Lh[(size_t)row*HF + col]      = v;
                else          g_Rh[(size_t)row*HF + col - HH] = v;
            }
        }
}

// ---------------- pair GEMM: K=528 (16 feat chunks of 32 + 1 coord chunk of 16) ----------------
// BM=144 pair-rows (4 i x 36 j), BN=128, 384 threads (3m x 4n warps)
#define SM_A0 0
#define SM_A1 11520
#define SM_B0 23040
#define SM_B1 33280
#define SM_R0 43520
#define SM_R1 45824
#define SM_L  48128
#define SM_CS 52224
#define SM_TOT 52928

__device__ __forceinline__ void issue_loads(uint32_t smb, int t, int sel, int tid, int n0, int rbase){
    uint32_t Bb = smb + (sel ? SM_B1 : SM_B0);
    const char* bsrc = (const char*)g_Wt + (size_t)n0*1024 + (size_t)t*64;
    {
        int p = tid;
        cpa16(Bb + (p>>2)*80 + (p&3)*16, bsrc + (size_t)(p>>2)*1024 + (p&3)*16);
        if (tid < 128){
            int p2 = tid + 384;
            cpa16(Bb + (p2>>2)*80 + (p2&3)*16, bsrc + (size_t)(p2>>2)*1024 + (p2&3)*16);
        }
    }
    if (tid < 144){
        uint32_t rdst = smb + (sel ? SM_R1 : SM_R0) + (tid>>2)*64 + (tid&3)*16;
        const char* rsrc = (const char*)g_Rh + (size_t)(rbase + (tid>>2))*1024 + (size_t)t*64 + (tid&3)*16;
        cpa16(rdst, rsrc);
    }
    cpa_commit();
}

__device__ __forceinline__ void build_A(char* sm, int t, int sel, int tid,
                                        const int* ggq, const int* jq){
    const __half2* Lh2 = (const __half2*)(sm + SM_L);
    const __half2* Rh2 = (const __half2*)(sm + (sel ? SM_R1 : SM_R0));
    char* Ab = sm + (sel ? SM_A1 : SM_A0);
    int k2 = tid & 15;
#pragma unroll
    for (int q=0;q<6;q++){
        int row = (tid>>4) + 24*q;
        __half2 l = Lh2[ggq[q]*256 + t*16 + k2];
        __half2 r = Rh2[jq[q]*16 + k2];
        *reinterpret_cast<__half2*>(Ab + row*80 + k2*4) = __hmul2(l, r);
    }
}

__global__ void __launch_bounds__(384,2) pair_gemm(const float* __restrict__ mm,
                                                   const float* __restrict__ coords,
                                                   float* __restrict__ out){
    extern __shared__ char sm[];
    const int tid = threadIdx.x, w = tid>>5, lane = tid&31;
    const int n0 = blockIdx.x*128;
    const int by = blockIdx.y, b = by/9, ig = by - b*9;
    const int lrow0 = b*NR + ig*4, rbase = b*NR;
    const uint32_t smb = sm_u32(sm);
    const int mrow0 = (w % 3)*48, ncol0 = (w / 3)*32;

    int ggq[6], jq[6];
#pragma unroll
    for (int q=0;q<6;q++){
        int row = (tid>>4) + 24*q;
        ggq[q] = row/36; jq[q] = row - 36*ggq[q];
    }

    // load L (4 rows x 512 f16) and coords staging
    {
        const uint4* src = reinterpret_cast<const uint4*>(g_Lh + (size_t)lrow0*HF);
        uint4* dst = reinterpret_cast<uint4*>(sm + SM_L);
        if (tid < 256) dst[tid] = src[tid];
        float* cs = reinterpret_cast<float*>(sm + SM_CS);
        if (tid < 16) cs[tid] = coords[(lrow0 + (tid>>2))*CC + (tid&3)];
        else if (tid < 160){ int e = tid-16; cs[tid] = coords[(rbase + (e>>2))*CC + (e&3)]; }
    }

    float acc[3][4][4];
#pragma unroll
    for (int m=0;m<3;m++) for (int n=0;n<4;n++) for (int c=0;c<4;c++) acc[m][n][c]=0.f;

    issue_loads(smb, 0, 0, tid, n0, rbase);
    cpa_wait0();
    __syncthreads();
    build_A(sm, 0, 0, tid, ggq, jq);
    __syncthreads();

    for (int t=0; t<16; t++){
        const int sel = t & 1, nsel = sel ^ 1;
        if (t < 15) issue_loads(smb, t+1, nsel, tid, n0, rbase);

        const uint32_t ab = smb + (sel ? SM_A1 : SM_A0);
        const uint32_t bb = smb + (sel ? SM_B1 : SM_B0);
#pragma unroll
        for (int ks=0; ks<2; ks++){
            uint32_t a[3][4];
#pragma unroll
            for (int mf=0;mf<3;mf++)
                ldm_x4(a[mf], ab + (uint32_t)(mrow0 + mf*16 + (lane&15))*80 + ks*32 + ((lane>>4)<<4));
            uint32_t bf[2][4];
#pragma unroll
            for (int g=0; g<2; g++)
                ldm_x4(bf[g], bb + (uint32_t)(ncol0 + g*16 + (lane&15))*80 + ks*32 + ((lane>>4)<<4));
#pragma unroll
            for (int mf=0;mf<3;mf++)
#pragma unroll
                for (int nf=0;nf<4;nf++){
                    int g = nf>>1, hi = nf&1;
                    mma16816(acc[mf][nf], a[mf], bf[g][hi], bf[g][hi+2]);
                }
        }

        cpa_wait0();
        __syncthreads();
        if (t < 15) build_A(sm, t+1, nsel, tid, ggq, jq);
        __syncthreads();
    }

    // ---- coord chunk (K=16): A = outer(c_i,c_j)/64, B = T tile ----
    {
        if (tid < 256){
            int row = tid>>1, seg = tid&1;
            cpa16(smb + SM_B0 + row*80 + seg*16,
                  (const char*)g_T + (size_t)(n0+row)*32 + seg*16);
        }
        cpa_commit();
        if (tid < 144){
            const float* cs = reinterpret_cast<const float*>(sm + SM_CS);
            int gg = tid/36, j = tid - gg*36;
            float ci[4], cj[4];
#pragma unroll
            for (int p=0;p<4;p++){ ci[p] = cs[gg*4+p]; cj[p] = cs[16 + j*4 + p]; }
            char* Ab = sm + SM_A0;
#pragma unroll
            for (int e2=0;e2<8;e2++){
                int p0 = (e2*2)>>2, q0 = (e2*2)&3, p1 = (e2*2+1)>>2, q1 = (e2*2+1)&3;
                *reinterpret_cast<__half2*>(Ab + tid*80 + e2*4) =
                    __floats2half2_rn(ci[p0]*cj[q0]*0.015625f, ci[p1]*cj[q1]*0.015625f);
            }
        }
        cpa_wait0();
        __syncthreads();
        uint32_t a[3][4], bf[2][4];
#pragma unroll
        for (int mf=0;mf<3;mf++)
            ldm_x4(a[mf], smb + SM_A0 + (uint32_t)(mrow0 + mf*16 + (lane&15))*80 + ((lane>>4)<<4));
#pragma unroll
        for (int g=0; g<2; g++)
            ldm_x4(bf[g], smb + SM_B0 + (uint32_t)(ncol0 + g*16 + (lane&15))*80 + ((lane>>4)<<4));
#pragma unroll
        for (int mf=0;mf<3;mf++)
#pragma unroll
            for (int nf=0;nf<4;nf++){
                int g = nf>>1, hi = nf&1;
                mma16816(acc[mf][nf], a[mf], bf[g][hi], bf[g][hi+2]);
            }
    }
    __syncthreads();

    // epilogue: segmented max over j via smem atomicMax (monotone encoding)
    unsigned* redu = reinterpret_cast<unsigned*>(sm);
    redu[tid] = 0u;
    if (tid < 128) redu[tid+384] = 0u;
    __syncthreads();
#pragma unroll
    for (int mf=0;mf<3;mf++)
#pragma unroll
        for (int hi=0;hi<2;hi++){
            int row = mrow0 + mf*16 + hi*8 + (lane>>2);
            int gg = row/36;
#pragma unroll
            for (int nf=0;nf<4;nf++)
#pragma unroll
                for (int cj=0;cj<2;cj++){
                    int col = ncol0 + nf*8 + (lane&3)*2 + cj;
                    atomicMax(&redu[gg*128 + col], f2mono(acc[mf][nf][hi*2+cj]));
                }
        }
    __syncthreads();
    for (int idx = tid; idx < 512; idx += 384){
        int gg = idx>>7, col = idx&127;
        float v = mono2f(redu[idx]);
        size_t o = (size_t)(lrow0 + gg)*DD + n0 + col;
        out[o] = v + mm[o];
    }
}

// ---------------- launch ----------------
extern "C" void kernel_launch(void* const* d_in, const int* in_sizes, int n_in,
                              void* d_out, int out_size){
    (void)in_sizes; (void)n_in; (void)out_size;
    const float* mm     = (const float*)d_in[0];
    const float* coords = (const float*)d_in[1];
    const float* W_cl   = (const float*)d_in[2];
    const float* W_cr   = (const float*)d_in[3];
    const float* W_cout = (const float*)d_in[4];
    const float* W_fl   = (const float*)d_in[5];
    const float* W_fr   = (const float*)d_in[6];
    const float* W_fout = (const float*)d_in[7];
    float* out = (float*)d_out;

    cudaFuncSetAttribute(pair_gemm, cudaFuncAttributeMaxDynamicSharedMemorySize, SM_TOT);

    prep_mmh    <<<1152, 256>>>(mm);
    prep_w_out_t<<<dim3(32,16), 256>>>(W_fout);
    prep_w_in_t <<<dim3(16,64), 256>>>(W_fl, W_fr);
    prep_T      <<<16, 128>>>(W_cl, W_cr, W_cout);
    stage1_gemm <<<dim3(16,18), 128>>>();
    pair_gemm   <<<dim3(16,288), 384, SM_TOT>>>(mm, coords, out);
}

// round 8
// speedup vs baseline: 3.9718x; 1.0986x over previous
#include <cuda_runtime.h>
#include <cuda_fp16.h>
#include <cstdint>

#define BB 32
#define NR 36
#define DD 2048
#define CC 4
#define HH 512
#define HF 512
#define NROWS (BB*NR)   // 1152

// Scratch (static device globals)
__device__ __half g_mmh [NROWS*DD];   // mm in f16
__device__ __half g_Lh  [NROWS*HF];   // fl f16
__device__ __half g_Rh  [NROWS*HF];   // fr f16
__device__ __half g_Wt  [DD*HF];      // W_fout^T: [d][k]
__device__ __half g_WffT[1024*DD];    // [h][k] fused (W_fl|W_fr) transposed
__device__ __half g_T   [DD*16];      // coord tensor T[d][p*4+q] * 64
__device__ float  g_Tp  [4][DD*16];   // h-split partials for T

// ---------------- helpers ----------------
__device__ __forceinline__ uint32_t sm_u32(const void* p){
    uint32_t a;
    asm("{ .reg .u64 t; cvta.to.shared.u64 t, %1; cvt.u32.u64 %0, t; }" : "=r"(a) : "l"(p));
    return a;
}
__device__ __forceinline__ void mma16816(float c[4], const uint32_t a[4], const uint32_t b0, const uint32_t b1){
    asm volatile("mma.sync.aligned.m16n8k16.row.col.f32.f16.f16.f32 "
                 "{%0,%1,%2,%3}, {%4,%5,%6,%7}, {%8,%9}, {%0,%1,%2,%3};\n"
                 : "+f"(c[0]), "+f"(c[1]), "+f"(c[2]), "+f"(c[3])
                 : "r"(a[0]), "r"(a[1]), "r"(a[2]), "r"(a[3]), "r"(b0), "r"(b1));
}
__device__ __forceinline__ void ldm_x4(uint32_t d[4], uint32_t addr){
    asm volatile("ldmatrix.sync.aligned.m8n8.x4.shared.b16 {%0,%1,%2,%3}, [%4];"
                 : "=r"(d[0]), "=r"(d[1]), "=r"(d[2]), "=r"(d[3]) : "r"(addr));
}
__device__ __forceinline__ void cpa16(uint32_t dst, const void* src){
    asm volatile("cp.async.cg.shared.global [%0], [%1], 16;"
                 :: "r"(dst), "l"(__cvta_generic_to_global(src)) : "memory");
}
__device__ __forceinline__ void cpa_commit(){ asm volatile("cp.async.commit_group;" ::: "memory"); }
__device__ __forceinline__ void cpa_wait0(){ asm volatile("cp.async.wait_group 0;" ::: "memory"); }
__device__ __forceinline__ void cpa_wait1(){ asm volatile("cp.async.wait_group 1;" ::: "memory"); }
__device__ __forceinline__ unsigned f2mono(float v){
    unsigned b = __float_as_uint(v);
    return (b & 0x80000000u) ? ~b : (b | 0x80000000u);
}
__device__ __forceinline__ float mono2f(unsigned u){
    return (u & 0x80000000u) ? __uint_as_float(u ^ 0x80000000u) : __uint_as_float(~u);
}

// ---------------- prep kernels ----------------
__global__ void prep_mmh(const float* __restrict__ mm){
    int i = blockIdx.x*256 + threadIdx.x;        // 294912 total
    const float4* s = reinterpret_cast<const float4*>(mm);
    float4 v0 = s[i*2], v1 = s[i*2+1];
    __half2* d = reinterpret_cast<__half2*>(g_mmh) + i*4;
    d[0] = __floats2half2_rn(v0.x, v0.y);
    d[1] = __floats2half2_rn(v0.z, v0.w);
    d[2] = __floats2half2_rn(v1.x, v1.y);
    d[3] = __floats2half2_rn(v1.z, v1.w);
}
// W_fout [512][2048] -> g_Wt [2048][512]
__global__ void prep_w_out_t(const float* __restrict__ Wf){
    __shared__ float ts[64][33];
    int tid = threadIdx.x;
    int d0 = blockIdx.x*64, k0 = blockIdx.y*32;
#pragma unroll
    for (int q=0;q<8;q++){
        int idx = tid + 256*q;
        int kk = idx>>6, dd = idx&63;
        ts[dd][kk] = Wf[(size_t)(k0+kk)*DD + d0 + dd];
    }
    __syncthreads();
    __half2* Wt2 = reinterpret_cast<__half2*>(g_Wt);
#pragma unroll
    for (int q=0;q<4;q++){
        int idx = tid + 256*q;
        int dd = idx>>4, kk2 = idx&15;
        Wt2[(size_t)(d0+dd)*(HF/2) + (k0>>1) + kk2] =
            __floats2half2_rn(ts[dd][kk2*2], ts[dd][kk2*2+1]);
    }
}
// (W_fl|W_fr) [2048][1024] -> g_WffT [1024][2048]
__global__ void prep_w_in_t(const float* __restrict__ Wfl, const float* __restrict__ Wfr){
    __shared__ float ts[64][33];
    int tid = threadIdx.x;
    int h0 = blockIdx.x*64, k0 = blockIdx.y*32;
#pragma unroll
    for (int q=0;q<8;q++){
        int idx = tid + 256*q;
        int kk = idx>>6, hh = idx&63;
        int h = h0 + hh, k = k0 + kk;
        ts[hh][kk] = (h < HH) ? Wfl[(size_t)k*HH + h] : Wfr[(size_t)k*HH + h - HH];
    }
    __syncthreads();
    __half2* W2 = reinterpret_cast<__half2*>(g_WffT);
#pragma unroll
    for (int q=0;q<4;q++){
        int idx = tid + 256*q;
        int hh = idx>>4, kk2 = idx&15;
        W2[(size_t)(h0+hh)*(DD/2) + (k0>>1) + kk2] =
            __floats2half2_rn(ts[hh][kk2*2], ts[hh][kk2*2+1]);
    }
}
// Partial T: g_Tp[hc][d*16+p*4+q] = sum_{h in chunk} Wcl[p][h]*Wcr[q][h]*Wcout[h][d]
__global__ void prep_T_part(const float* __restrict__ Wcl, const float* __restrict__ Wcr,
                            const float* __restrict__ Wc){
    __shared__ float scl[4][128], scr[4][128];
    int tid = threadIdx.x;                      // 128 threads
    int hbase = blockIdx.y*128;
    for (int i = tid; i < 4*128; i += 128){
        int p = i>>7, hh = i&127;
        scl[p][hh] = Wcl[p*HH + hbase + hh];
        scr[p][hh] = Wcr[p*HH + hbase + hh];
    }
    __syncthreads();
    int d = blockIdx.x*128 + tid;
    float acc[16];
#pragma unroll
    for (int e=0;e<16;e++) acc[e]=0.f;
    for (int h0=0; h0<128; h0+=8){
        float wc[8];
#pragma unroll
        for (int u=0;u<8;u++) wc[u] = Wc[(size_t)(hbase+h0+u)*DD + d];
#pragma unroll
        for (int u=0;u<8;u++){
            int hh = h0+u;
#pragma unroll
            for (int p=0;p<4;p++){
                float a = scl[p][hh]*wc[u];
#pragma unroll
                for (int q=0;q<4;q++) acc[p*4+q] = fmaf(a, scr[q][hh], acc[p*4+q]);
            }
        }
    }
#pragma unroll
    for (int e=0;e<16;e++) g_Tp[blockIdx.y][d*16+e] = acc[e];
}
__global__ void prep_T_final(){
    int i = blockIdx.x*256 + threadIdx.x;       // 32768 total
    float s = g_Tp[0][i] + g_Tp[1][i] + g_Tp[2][i] + g_Tp[3][i];
    g_T[i] = __float2half(s*64.0f);
}

// ---------------- stage 1: [fl|fr] = mm @ [W_fl|W_fr] (M=1152,K=2048,N=1024) ----------------
#define S1_A0 0
#define S1_A1 5120
#define S1_B0 10240
#define S1_B1 15360

__device__ __forceinline__ void s1_issue(uint32_t smb, int t, int sel, int tid, int m0, int n0){
    uint32_t Ab = smb + (sel ? S1_A1 : S1_A0);
    uint32_t Bb = smb + (sel ? S1_B1 : S1_B0);
#pragma unroll
    for (int q=0;q<2;q++){
        int idx = tid + 128*q, row = idx>>2, seg = idx&3;
        cpa16(Ab + row*80 + seg*16, (const char*)g_mmh  + (size_t)(m0+row)*4096 + t*64 + seg*16);
        cpa16(Bb + row*80 + seg*16, (const char*)g_WffT + (size_t)(n0+row)*4096 + t*64 + seg*16);
    }
    cpa_commit();
}

__global__ __launch_bounds__(128) void stage1_gemm(){
    __shared__ char sm[20480];
    uint32_t smb = sm_u32(sm);
    int tid = threadIdx.x, warp = tid>>5, lane = tid&31;
    int n0 = blockIdx.x*64, m0 = blockIdx.y*64;
    int wm = (warp&1)*32, wn = (warp>>1)*32;
    float acc[2][4][4];
#pragma unroll
    for (int a=0;a<2;a++) for (int b=0;b<4;b++) for (int c=0;c<4;c++) acc[a][b][c]=0.f;

    s1_issue(smb, 0, 0, tid, m0, n0);
    for (int t=0; t<64; t++){
        int sel = t&1;
        if (t<63){ s1_issue(smb, t+1, sel^1, tid, m0, n0); cpa_wait1(); }
        else cpa_wait0();
        __syncthreads();
        uint32_t Ab = smb + (sel ? S1_A1 : S1_A0);
        uint32_t Bb = smb + (sel ? S1_B1 : S1_B0);
#pragma unroll
        for (int ks=0; ks<2; ks++){
            uint32_t a[2][4], bfr[2][4];
#pragma unroll
            for (int mf=0;mf<2;mf++)
                ldm_x4(a[mf], Ab + (uint32_t)(wm+mf*16+(lane&15))*80 + ks*32 + ((lane>>4)<<4));
#pragma unroll
            for (int g=0;g<2;g++)
                ldm_x4(bfr[g], Bb + (uint32_t)(wn+g*16+(lane&15))*80 + ks*32 + ((lane>>4)<<4));
#pragma unroll
            for (int mf=0;mf<2;mf++)
#pragma unroll
                for (int g=0;g<2;g++)
#pragma unroll
                    for (int hi=0;hi<2;hi++)
                        mma16816(acc[mf][g*2+hi], a[mf], bfr[g][hi], bfr[g][hi+2]);
        }
        __syncthreads();
    }
#pragma unroll
    for (int mf=0;mf<2;mf++)
#pragma unroll
        for (int nf=0;nf<4;nf++){
            int g = nf>>1, hi = nf&1;
#pragma unroll
            for (int ci=0;ci<4;ci++){
                int row = m0 + wm + mf*16 + (lane>>2) + (ci>>1)*8;
                int col = n0 + wn + g*16 + hi*8 + (lane&3)*2 + (ci&1);
                __half v = __float2half(acc[mf][nf][ci]);
                if (col < HH) g_Lh[(size_t)row*HF + col]      = v;
                else          g_Rh[(size_t)row*HF + col - HH] = v;
            }
        }
}

// ---------------- pair GEMM: K=528 (16 feat chunks of 32 + 1 coord chunk of 16) ----------------
#define SM_A0 0
#define SM_A1 11520
#define SM_B0 23040
#define SM_B1 33280
#define SM_R0 43520
#define SM_R1 45824
#define SM_L  48128
#define SM_CS 52224
#define SM_TOT 52928

__device__ __forceinline__ void issue_loads(uint32_t smb, int t, int sel, int tid, int n0, int rbase){
    uint32_t Bb = smb + (sel ? SM_B1 : SM_B0);
    const char* bsrc = (const char*)g_Wt + (size_t)n0*1024 + (size_t)t*64;
    {
        int p = tid;
        cpa16(Bb + (p>>2)*80 + (p&3)*16, bsrc + (size_t)(p>>2)*1024 + (p&3)*16);
        if (tid < 128){
            int p2 = tid + 384;
            cpa16(Bb + (p2>>2)*80 + (p2&3)*16, bsrc + (size_t)(p2>>2)*1024 + (p2&3)*16);
        }
    }
    if (tid < 144){
        uint32_t rdst = smb + (sel ? SM_R1 : SM_R0) + (tid>>2)*64 + (tid&3)*16;
        const char* rsrc = (const char*)g_Rh + (size_t)(rbase + (tid>>2))*1024 + (size_t)t*64 + (tid&3)*16;
        cpa16(rdst, rsrc);
    }
    cpa_commit();
}

__device__ __forceinline__ void build_A(char* sm, int t, int sel, int tid,
                                        const int* ggq, const int* jq){
    const __half2* Lh2 = (const __half2*)(sm + SM_L);
    const __half2* Rh2 = (const __half2*)(sm + (sel ? SM_R1 : SM_R0));
    char* Ab = sm + (sel ? SM_A1 : SM_A0);
    int k2 = tid & 15;
#pragma unroll
    for (int q=0;q<6;q++){
        int row = (tid>>4) + 24*q;
        __half2 l = Lh2[ggq[q]*256 + t*16 + k2];
        __half2 r = Rh2[jq[q]*16 + k2];
        *reinterpret_cast<__half2*>(Ab + row*80 + k2*4) = __hmul2(l, r);
    }
}

__global__ void __launch_bounds__(384,2) pair_gemm(const float* __restrict__ mm,
                                                   const float* __restrict__ coords,
                                                   float* __restrict__ out){
    extern __shared__ char sm[];
    const int tid = threadIdx.x, w = tid>>5, lane = tid&31;
    const int n0 = blockIdx.x*128;
    const int by = blockIdx.y, b = by/9, ig = by - b*9;
    const int lrow0 = b*NR + ig*4, rbase = b*NR;
    const uint32_t smb = sm_u32(sm);
    const int mrow0 = (w % 3)*48, ncol0 = (w / 3)*32;

    int ggq[6], jq[6];
#pragma unroll
    for (int q=0;q<6;q++){
        int row = (tid>>4) + 24*q;
        ggq[q] = row/36; jq[q] = row - 36*ggq[q];
    }

    {
        const uint4* src = reinterpret_cast<const uint4*>(g_Lh + (size_t)lrow0*HF);
        uint4* dst = reinterpret_cast<uint4*>(sm + SM_L);
        if (tid < 256) dst[tid] = src[tid];
        float* cs = reinterpret_cast<float*>(sm + SM_CS);
        if (tid < 16) cs[tid] = coords[(lrow0 + (tid>>2))*CC + (tid&3)];
        else if (tid < 160){ int e = tid-16; cs[tid] = coords[(rbase + (e>>2))*CC + (e&3)]; }
    }

    float acc[3][4][4];
#pragma unroll
    for (int m=0;m<3;m++) for (int n=0;n<4;n++) for (int c=0;c<4;c++) acc[m][n][c]=0.f;

    issue_loads(smb, 0, 0, tid, n0, rbase);
    cpa_wait0();
    __syncthreads();
    build_A(sm, 0, 0, tid, ggq, jq);
    __syncthreads();

    for (int t=0; t<16; t++){
        const int sel = t & 1, nsel = sel ^ 1;
        if (t < 15) issue_loads(smb, t+1, nsel, tid, n0, rbase);

        const uint32_t ab = smb + (sel ? SM_A1 : SM_A0);
        const uint32_t bb = smb + (sel ? SM_B1 : SM_B0);
#pragma unroll
        for (int ks=0; ks<2; ks++){
            uint32_t a[3][4];
#pragma unroll
            for (int mf=0;mf<3;mf++)
                ldm_x4(a[mf], ab + (uint32_t)(mrow0 + mf*16 + (lane&15))*80 + ks*32 + ((lane>>4)<<4));
            uint32_t bf[2][4];
#pragma unroll
            for (int g=0; g<2; g++)
                ldm_x4(bf[g], bb + (uint32_t)(ncol0 + g*16 + (lane&15))*80 + ks*32 + ((lane>>4)<<4));
#pragma unroll
            for (int mf=0;mf<3;mf++)
#pragma unroll
                for (int nf=0;nf<4;nf++){
                    int g = nf>>1, hi = nf&1;
                    mma16816(acc[mf][nf], a[mf], bf[g][hi], bf[g][hi+2]);
                }
        }

        cpa_wait0();
        __syncthreads();
        if (t < 15) build_A(sm, t+1, nsel, tid, ggq, jq);
        __syncthreads();
    }

    // ---- coord chunk (K=16): A = outer(c_i,c_j)/64, B = T tile ----
    {
        if (tid < 256){
            int row = tid>>1, seg = tid&1;
            cpa16(smb + SM_B0 + row*80 + seg*16,
                  (const char*)g_T + (size_t)(n0+row)*32 + seg*16);
        }
        cpa_commit();
        if (tid < 144){
            const float* cs = reinterpret_cast<const float*>(sm + SM_CS);
            int gg = tid/36, j = tid - gg*36;
            float ci[4], cj[4];
#pragma unroll
            for (int p=0;p<4;p++){ ci[p] = cs[gg*4+p]; cj[p] = cs[16 + j*4 + p]; }
            char* Ab = sm + SM_A0;
#pragma unroll
            for (int e2=0;e2<8;e2++){
                int p0 = (e2*2)>>2, q0 = (e2*2)&3, p1 = (e2*2+1)>>2, q1 = (e2*2+1)&3;
                *reinterpret_cast<__half2*>(Ab + tid*80 + e2*4) =
                    __floats2half2_rn(ci[p0]*cj[q0]*0.015625f, ci[p1]*cj[q1]*0.015625f);
            }
        }
        cpa_wait0();
        __syncthreads();
        uint32_t a[3][4], bf[2][4];
#pragma unroll
        for (int mf=0;mf<3;mf++)
            ldm_x4(a[mf], smb + SM_A0 + (uint32_t)(mrow0 + mf*16 + (lane&15))*80 + ((lane>>4)<<4));
#pragma unroll
        for (int g=0; g<2; g++)
            ldm_x4(bf[g], smb + SM_B0 + (uint32_t)(ncol0 + g*16 + (lane&15))*80 + ((lane>>4)<<4));
#pragma unroll
        for (int mf=0;mf<3;mf++)
#pragma unroll
            for (int nf=0;nf<4;nf++){
                int g = nf>>1, hi = nf&1;
                mma16816(acc[mf][nf], a[mf], bf[g][hi], bf[g][hi+2]);
            }
    }
    __syncthreads();

    // epilogue: segmented max over j via smem atomicMax (monotone encoding)
    unsigned* redu = reinterpret_cast<unsigned*>(sm);
    redu[tid] = 0u;
    if (tid < 128) redu[tid+384] = 0u;
    __syncthreads();
#pragma unroll
    for (int mf=0;mf<3;mf++)
#pragma unroll
        for (int hi=0;hi<2;hi++){
            int row = mrow0 + mf*16 + hi*8 + (lane>>2);
            int gg = row/36;
#pragma unroll
            for (int nf=0;nf<4;nf++)
#pragma unroll
                for (int cj=0;cj<2;cj++){
                    int col = ncol0 + nf*8 + (lane&3)*2 + cj;
                    atomicMax(&redu[gg*128 + col], f2mono(acc[mf][nf][hi*2+cj]));
                }
        }
    __syncthreads();
    for (int idx = tid; idx < 512; idx += 384){
        int gg = idx>>7, col = idx&127;
        float v = mono2f(redu[idx]);
        size_t o = (size_t)(lrow0 + gg)*DD + n0 + col;
        out[o] = v + mm[o];
    }
}

// ---------------- launch ----------------
extern "C" void kernel_launch(void* const* d_in, const int* in_sizes, int n_in,
                              void* d_out, int out_size){
    (void)in_sizes; (void)n_in; (void)out_size;
    const float* mm     = (const float*)d_in[0];
    const float* coords = (const float*)d_in[1];
    const float* W_cl   = (const float*)d_in[2];
    const float* W_cr   = (const float*)d_in[3];
    const float* W_cout = (const float*)d_in[4];
    const float* W_fl   = (const float*)d_in[5];
    const float* W_fr   = (const float*)d_in[6];
    const float* W_fout = (const float*)d_in[7];
    float* out = (float*)d_out;

    cudaFuncSetAttribute(pair_gemm, cudaFuncAttributeMaxDynamicSharedMemorySize, SM_TOT);

    prep_mmh    <<<1152, 256>>>(mm);
    prep_w_out_t<<<dim3(32,16), 256>>>(W_fout);
    prep_w_in_t <<<dim3(16,64), 256>>>(W_fl, W_fr);
    prep_T_part <<<dim3(16,4), 128>>>(W_cl, W_cr, W_cout);
    prep_T_final<<<128, 256>>>();
    stage1_gemm <<<dim3(16,18), 128>>>();
    pair_gemm   <<<dim3(16,288), 384, SM_TOT>>>(mm, coords, out);
}

// round 10
// speedup vs baseline: 4.1181x; 1.0368x over previous
#include <cuda_runtime.h>
#include <cuda_fp16.h>
#include <cstdint>

#define BB 32
#define NR 36
#define DD 2048
#define CC 4
#define HH 512
#define HF 512
#define NROWS (BB*NR)   // 1152

// Scratch (static device globals)
__device__ __half g_mmh [NROWS*DD];   // mm in f16
__device__ __half g_Lh  [NROWS*HF];   // fl f16
__device__ __half g_Rh  [NROWS*HF];   // fr f16
__device__ __half g_Wt  [DD*HF];      // W_fout^T: [d][k]
__device__ __half g_WffT[1024*DD];    // [h][k] fused (W_fl|W_fr) transposed
__device__ __half g_T   [DD*16];      // coord tensor T[d][p*4+q] * 64
__device__ float  g_Tp  [16][DD*16];  // h-split partials for T

// ---------------- helpers ----------------
__device__ __forceinline__ uint32_t sm_u32(const void* p){
    uint32_t a;
    asm("{ .reg .u64 t; cvta.to.shared.u64 t, %1; cvt.u32.u64 %0, t; }" : "=r"(a) : "l"(p));
    return a;
}
__device__ __forceinline__ void mma16816(float c[4], const uint32_t a[4], const uint32_t b0, const uint32_t b1){
    asm volatile("mma.sync.aligned.m16n8k16.row.col.f32.f16.f16.f32 "
                 "{%0,%1,%2,%3}, {%4,%5,%6,%7}, {%8,%9}, {%0,%1,%2,%3};\n"
                 : "+f"(c[0]), "+f"(c[1]), "+f"(c[2]), "+f"(c[3])
                 : "r"(a[0]), "r"(a[1]), "r"(a[2]), "r"(a[3]), "r"(b0), "r"(b1));
}
__device__ __forceinline__ void ldm_x4(uint32_t d[4], uint32_t addr){
    asm volatile("ldmatrix.sync.aligned.m8n8.x4.shared.b16 {%0,%1,%2,%3}, [%4];"
                 : "=r"(d[0]), "=r"(d[1]), "=r"(d[2]), "=r"(d[3]) : "r"(addr));
}
__device__ __forceinline__ void cpa16(uint32_t dst, const void* src){
    asm volatile("cp.async.cg.shared.global [%0], [%1], 16;"
                 :: "r"(dst), "l"(__cvta_generic_to_global(src)) : "memory");
}
__device__ __forceinline__ void cpa_commit(){ asm volatile("cp.async.commit_group;" ::: "memory"); }
__device__ __forceinline__ void cpa_wait0(){ asm volatile("cp.async.wait_group 0;" ::: "memory"); }
__device__ __forceinline__ void cpa_wait1(){ asm volatile("cp.async.wait_group 1;" ::: "memory"); }
__device__ __forceinline__ unsigned f2mono(float v){
    unsigned b = __float_as_uint(v);
    return (b & 0x80000000u) ? ~b : (b | 0x80000000u);
}
__device__ __forceinline__ float mono2f(unsigned u){
    return (u & 0x80000000u) ? __uint_as_float(u ^ 0x80000000u) : __uint_as_float(~u);
}

// ---------------- prep kernels ----------------
__global__ void prep_mmh(const float* __restrict__ mm){
    int i = blockIdx.x*256 + threadIdx.x;        // 294912 total
    const float4* s = reinterpret_cast<const float4*>(mm);
    float4 v0 = s[i*2], v1 = s[i*2+1];
    __half2* d = reinterpret_cast<__half2*>(g_mmh) + i*4;
    d[0] = __floats2half2_rn(v0.x, v0.y);
    d[1] = __floats2half2_rn(v0.z, v0.w);
    d[2] = __floats2half2_rn(v1.x, v1.y);
    d[3] = __floats2half2_rn(v1.z, v1.w);
}
// W_fout [512][2048] -> g_Wt [2048][512]
__global__ void prep_w_out_t(const float* __restrict__ Wf){
    __shared__ float ts[64][33];
    int tid = threadIdx.x;
    int d0 = blockIdx.x*64, k0 = blockIdx.y*32;
#pragma unroll
    for (int q=0;q<8;q++){
        int idx = tid + 256*q;
        int kk = idx>>6, dd = idx&63;
        ts[dd][kk] = Wf[(size_t)(k0+kk)*DD + d0 + dd];
    }
    __syncthreads();
    __half2* Wt2 = reinterpret_cast<__half2*>(g_Wt);
#pragma unroll
    for (int q=0;q<4;q++){
        int idx = tid + 256*q;
        int dd = idx>>4, kk2 = idx&15;
        Wt2[(size_t)(d0+dd)*(HF/2) + (k0>>1) + kk2] =
            __floats2half2_rn(ts[dd][kk2*2], ts[dd][kk2*2+1]);
    }
}
// (W_fl|W_fr) [2048][1024] -> g_WffT [1024][2048]
__global__ void prep_w_in_t(const float* __restrict__ Wfl, const float* __restrict__ Wfr){
    __shared__ float ts[64][33];
    int tid = threadIdx.x;
    int h0 = blockIdx.x*64, k0 = blockIdx.y*32;
#pragma unroll
    for (int q=0;q<8;q++){
        int idx = tid + 256*q;
        int kk = idx>>6, hh = idx&63;
        int h = h0 + hh, k = k0 + kk;
        ts[hh][kk] = (h < HH) ? Wfl[(size_t)k*HH + h] : Wfr[(size_t)k*HH + h - HH];
    }
    __syncthreads();
    __half2* W2 = reinterpret_cast<__half2*>(g_WffT);
#pragma unroll
    for (int q=0;q<4;q++){
        int idx = tid + 256*q;
        int hh = idx>>4, kk2 = idx&15;
        W2[(size_t)(h0+hh)*(DD/2) + (k0>>1) + kk2] =
            __floats2half2_rn(ts[hh][kk2*2], ts[hh][kk2*2+1]);
    }
}
// Partial T: g_Tp[hc][d*16+p*4+q] over 32-h chunks, 256 d per block
__global__ __launch_bounds__(256) void prep_T_part(const float* __restrict__ Wcl,
                                                   const float* __restrict__ Wcr,
                                                   const float* __restrict__ Wc){
    __shared__ float scl[4][32], scr[4][32];
    int tid = threadIdx.x;
    int hbase = blockIdx.y*32;
    if (tid < 128){
        int p = tid>>5, hh = tid&31;
        scl[p][hh] = Wcl[p*HH + hbase + hh];
        scr[p][hh] = Wcr[p*HH + hbase + hh];
    }
    __syncthreads();
    int d = blockIdx.x*256 + tid;
    float acc[16];
#pragma unroll
    for (int e=0;e<16;e++) acc[e]=0.f;
#pragma unroll
    for (int h0=0; h0<32; h0+=8){
        float wc[8];
#pragma unroll
        for (int u=0;u<8;u++) wc[u] = Wc[(size_t)(hbase+h0+u)*DD + d];
#pragma unroll
        for (int u=0;u<8;u++){
            int hh = h0+u;
#pragma unroll
            for (int p=0;p<4;p++){
                float a = scl[p][hh]*wc[u];
#pragma unroll
                for (int q=0;q<4;q++) acc[p*4+q] = fmaf(a, scr[q][hh], acc[p*4+q]);
            }
        }
    }
#pragma unroll
    for (int e=0;e<16;e++) g_Tp[blockIdx.y][d*16+e] = acc[e];
}
__global__ void prep_T_final(){
    int i = blockIdx.x*256 + threadIdx.x;       // 32768 total
    float s = 0.f;
#pragma unroll
    for (int p=0;p<16;p++) s += g_Tp[p][i];
    g_T[i] = __float2half(s*64.0f);
}

// ---------------- stage 1: [fl|fr] = mm @ [W_fl|W_fr] (M=1152,K=2048,N=1024) ----------------
// BM=64, BN=128, BK=32, 256 threads (2m x 4n warps of 32x32), 144 CTAs
#define S1_A0 0
#define S1_A1 5120
#define S1_B0 10240
#define S1_B1 20480

__device__ __forceinline__ void s1_issue(uint32_t smb, int t, int sel, int tid, int m0, int n0){
    uint32_t Ab = smb + (sel ? S1_A1 : S1_A0);
    uint32_t Bb = smb + (sel ? S1_B1 : S1_B0);
    {   // A: 64 rows x 4 segs = 256
        int row = tid>>2, seg = tid&3;
        cpa16(Ab + row*80 + seg*16, (const char*)g_mmh + (size_t)(m0+row)*4096 + t*64 + seg*16);
    }
#pragma unroll
    for (int q=0;q<2;q++){  // B: 128 rows x 4 segs = 512
        int idx = tid + 256*q, row = idx>>2, seg = idx&3;
        cpa16(Bb + row*80 + seg*16, (const char*)g_WffT + (size_t)(n0+row)*4096 + t*64 + seg*16);
    }
    cpa_commit();
}

__global__ __launch_bounds__(256) void stage1_gemm(){
    __shared__ char sm[30720];
    uint32_t smb = sm_u32(sm);
    int tid = threadIdx.x, warp = tid>>5, lane = tid&31;
    int n0 = blockIdx.x*128, m0 = blockIdx.y*64;
    int wm = (warp&1)*32, wn = (warp>>1)*32;
    float acc[2][4][4];
#pragma unroll
    for (int a=0;a<2;a++) for (int b=0;b<4;b++) for (int c=0;c<4;c++) acc[a][b][c]=0.f;

    s1_issue(smb, 0, 0, tid, m0, n0);
    for (int t=0; t<64; t++){
        int sel = t&1;
        if (t<63){ s1_issue(smb, t+1, sel^1, tid, m0, n0); cpa_wait1(); }
        else cpa_wait0();
        __syncthreads();
        uint32_t Ab = smb + (sel ? S1_A1 : S1_A0);
        uint32_t Bb = smb + (sel ? S1_B1 : S1_B0);
#pragma unroll
        for (int ks=0; ks<2; ks++){
            uint32_t a[2][4], bfr[2][4];
#pragma unroll
            for (int mf=0;mf<2;mf++)
                ldm_x4(a[mf], Ab + (uint32_t)(wm+mf*16+(lane&15))*80 + ks*32 + ((lane>>4)<<4));
#pragma unroll
            for (int g=0;g<2;g++)
                ldm_x4(bfr[g], Bb + (uint32_t)(wn+g*16+(lane&15))*80 + ks*32 + ((lane>>4)<<4));
#pragma unroll
            for (int mf=0;mf<2;mf++)
#pragma unroll
                for (int g=0;g<2;g++)
#pragma unroll
                    for (int hi=0;hi<2;hi++)
                        mma16816(acc[mf][g*2+hi], a[mf], bfr[g][hi], bfr[g][hi+2]);
        }
        __syncthreads();
    }
#pragma unroll
    for (int mf=0;mf<2;mf++)
#pragma unroll
        for (int nf=0;nf<4;nf++){
            int g = nf>>1, hi = nf&1;
#pragma unroll
            for (int ci=0;ci<4;ci++){
                int row = m0 + wm + mf*16 + (lane>>2) + (ci>>1)*8;
                int col = n0 + wn + g*16 + hi*8 + (lane&3)*2 + (ci&1);
                __half v = __float2half(acc[mf][nf][ci]);
                if (col < HH) g_Lh[(size_t)row*HF + col]      = v;
                else          g_Rh[(size_t)row*HF + col - HH] = v;
            }
        }
}

// ---------------- pair GEMM: K=528, triple-buffered B/R, double-buffered A ----------------
// BM=144 pair-rows (4 i x 36 j), BN=128, 384 threads (3m x 4n warps)
#define SM_A0 0
#define SM_A1 11520
#define SM_B0 23040          // 3 x 10240
#define SM_R0 53760          // 3 x 2304
#define SM_L  60672
#define SM_CS 64768
#define SM_TOT 65408

__device__ __forceinline__ void issue_loads(uint32_t smb, int t, int bsel, int tid, int n0, int rbase){
    uint32_t Bb = smb + SM_B0 + bsel*10240;
    const char* bsrc = (const char*)g_Wt + (size_t)n0*1024 + (size_t)t*64;
    {
        int p = tid;
        cpa16(Bb + (p>>2)*80 + (p&3)*16, bsrc + (size_t)(p>>2)*1024 + (p&3)*16);
        if (tid < 128){
            int p2 = tid + 384;
            cpa16(Bb + (p2>>2)*80 + (p2&3)*16, bsrc + (size_t)(p2>>2)*1024 + (p2&3)*16);
        }
    }
    if (tid < 144){
        uint32_t rdst = smb + SM_R0 + bsel*2304 + (tid>>2)*64 + (tid&3)*16;
        const char* rsrc = (const char*)g_Rh + (size_t)(rbase + (tid>>2))*1024 + (size_t)t*64 + (tid&3)*16;
        cpa16(rdst, rsrc);
    }
    cpa_commit();
}

__device__ __forceinline__ void build_A(char* sm, int t, int asel, int rsel, int tid,
                                        const int* ggq, const int* jq){
    const __half2* Lh2 = (const __half2*)(sm + SM_L);
    const __half2* Rh2 = (const __half2*)(sm + SM_R0 + rsel*2304);
    char* Ab = sm + (asel ? SM_A1 : SM_A0);
    int k2 = tid & 15;
#pragma unroll
    for (int q=0;q<6;q++){
        int row = (tid>>4) + 24*q;
        __half2 l = Lh2[ggq[q]*256 + t*16 + k2];
        __half2 r = Rh2[jq[q]*16 + k2];
        *reinterpret_cast<__half2*>(Ab + row*80 + k2*4) = __hmul2(l, r);
    }
}

__global__ void __launch_bounds__(384,2) pair_gemm(const float* __restrict__ mm,
                                                   const float* __restrict__ coords,
                                                   float* __restrict__ out){
    extern __shared__ char sm[];
    const int tid = threadIdx.x, w = tid>>5, lane = tid&31;
    const int n0 = blockIdx.x*128;
    const int by = blockIdx.y, b = by/9, ig = by - b*9;
    const int lrow0 = b*NR + ig*4, rbase = b*NR;
    const uint32_t smb = sm_u32(sm);
    const int mrow0 = (w % 3)*48, ncol0 = (w / 3)*32;

    int ggq[6], jq[6];
#pragma unroll
    for (int q=0;q<6;q++){
        int row = (tid>>4) + 24*q;
        ggq[q] = row/36; jq[q] = row - 36*ggq[q];
    }

    {
        const uint4* src = reinterpret_cast<const uint4*>(g_Lh + (size_t)lrow0*HF);
        uint4* dst = reinterpret_cast<uint4*>(sm + SM_L);
        if (tid < 256) dst[tid] = src[tid];
        float* cs = reinterpret_cast<float*>(sm + SM_CS);
        if (tid < 16) cs[tid] = coords[(lrow0 + (tid>>2))*CC + (tid&3)];
        else if (tid < 160){ int e = tid-16; cs[tid] = coords[(rbase + (e>>2))*CC + (e&3)]; }
    }

    float acc[3][4][4];
#pragma unroll
    for (int m=0;m<3;m++) for (int n=0;n<4;n++) for (int c=0;c<4;c++) acc[m][n][c]=0.f;

    // prologue: two chunks in flight
    issue_loads(smb, 0, 0, tid, n0, rbase);
    issue_loads(smb, 1, 1, tid, n0, rbase);
    cpa_wait1();
    __syncthreads();
    build_A(sm, 0, 0, 0, tid, ggq, jq);
    __syncthreads();

    for (int t=0; t<16; t++){
        const int bsel = t % 3, asel = t & 1;
        if (t < 14) issue_loads(smb, t+2, (t+2)%3, tid, n0, rbase);

        const uint32_t ab = smb + (asel ? SM_A1 : SM_A0);
        const uint32_t bb = smb + SM_B0 + bsel*10240;
#pragma unroll
        for (int ks=0; ks<2; ks++){
            uint32_t a[3][4];
#pragma unroll
            for (int mf=0;mf<3;mf++)
                ldm_x4(a[mf], ab + (uint32_t)(mrow0 + mf*16 + (lane&15))*80 + ks*32 + ((lane>>4)<<4));
            uint32_t bf[2][4];
#pragma unroll
            for (int g=0; g<2; g++)
                ldm_x4(bf[g], bb + (uint32_t)(ncol0 + g*16 + (lane&15))*80 + ks*32 + ((lane>>4)<<4));
#pragma unroll
            for (int mf=0;mf<3;mf++)
#pragma unroll
                for (int nf=0;nf<4;nf++){
                    int g = nf>>1, hi = nf&1;
                    mma16816(acc[mf][nf], a[mf], bf[g][hi], bf[g][hi+2]);
                }
        }

        if (t < 15){
            if (t < 14) cpa_wait1(); else cpa_wait0();
            __syncthreads();
            build_A(sm, t+1, asel^1, (t+1)%3, tid, ggq, jq);
        }
        __syncthreads();
    }

    // ---- coord chunk (K=16): A = outer(c_i,c_j)/64, B = T tile ----
    {
        if (tid < 256){
            int row = tid>>1, seg = tid&1;
            cpa16(smb + SM_B0 + row*80 + seg*16,
                  (const char*)g_T + (size_t)(n0+row)*32 + seg*16);
        }
        cpa_commit();
        if (tid < 144){
            const float* cs = reinterpret_cast<const float*>(sm + SM_CS);
            int gg = tid/36, j = tid - gg*36;
            float ci[4], cj[4];
#pragma unroll
            for (int p=0;p<4;p++){ ci[p] = cs[gg*4+p]; cj[p] = cs[16 + j*4 + p]; }
            char* Ab = sm + SM_A0;
#pragma unroll
            for (int e2=0;e2<8;e2++){
                int p0 = (e2*2)>>2, q0 = (e2*2)&3, p1 = (e2*2+1)>>2, q1 = (e2*2+1)&3;
                *reinterpret_cast<__half2*>(Ab + tid*80 + e2*4) =
                    __floats2half2_rn(ci[p0]*cj[q0]*0.015625f, ci[p1]*cj[q1]*0.015625f);
            }
        }
        cpa_wait0();
        __syncthreads();
        uint32_t a[3][4], bf[2][4];
#pragma unroll
        for (int mf=0;mf<3;mf++)
            ldm_x4(a[mf], smb + SM_A0 + (uint32_t)(mrow0 + mf*16 + (lane&15))*80 + ((lane>>4)<<4));
#pragma unroll
        for (int g=0; g<2; g++)
            ldm_x4(bf[g], smb + SM_B0 + (uint32_t)(ncol0 + g*16 + (lane&15))*80 + ((lane>>4)<<4));
#pragma unroll
        for (int mf=0;mf<3;mf++)
#pragma unroll
            for (int nf=0;nf<4;nf++){
                int g = nf>>1, hi = nf&1;
                mma16816(acc[mf][nf], a[mf], bf[g][hi], bf[g][hi+2]);
            }
    }
    __syncthreads();

    // epilogue: segmented max over j via smem atomicMax (monotone encoding)
    unsigned* redu = reinterpret_cast<unsigned*>(sm);
    redu[tid] = 0u;
    if (tid < 128) redu[tid+384] = 0u;
    __syncthreads();
#pragma unroll
    for (int mf=0;mf<3;mf++)
#pragma unroll
        for (int hi=0;hi<2;hi++){
            int row = mrow0 + mf*16 + hi*8 + (lane>>2);
            int gg = row/36;
#pragma unroll
            for (int nf=0;nf<4;nf++)
#pragma unroll
                for (int cj=0;cj<2;cj++){
                    int col = ncol0 + nf*8 + (lane&3)*2 + cj;
                    atomicMax(&redu[gg*128 + col], f2mono(acc[mf][nf][hi*2+cj]));
                }
        }
    __syncthreads();
    for (int idx = tid; idx < 512; idx += 384){
        int gg = idx>>7, col = idx&127;
        float v = mono2f(redu[idx]);
        size_t o = (size_t)(lrow0 + gg)*DD + n0 + col;
        out[o] = v + mm[o];
    }
}

// ---------------- launch ----------------
extern "C" void kernel_launch(void* const* d_in, const int* in_sizes, int n_in,
                              void* d_out, int out_size){
    (void)in_sizes; (void)n_in; (void)out_size;
    const float* mm     = (const float*)d_in[0];
    const float* coords = (const float*)d_in[1];
    const float* W_cl   = (const float*)d_in[2];
    const float* W_cr   = (const float*)d_in[3];
    const float* W_cout = (const float*)d_in[4];
    const float* W_fl   = (const float*)d_in[5];
    const float* W_fr   = (const float*)d_in[6];
    const float* W_fout = (const float*)d_in[7];
    float* out = (float*)d_out;

    cudaFuncSetAttribute(pair_gemm, cudaFuncAttributeMaxDynamicSharedMemorySize, SM_TOT);

    prep_mmh    <<<1152, 256>>>(mm);
    prep_w_out_t<<<dim3(32,16), 256>>>(W_fout);
    prep_w_in_t <<<dim3(16,64), 256>>>(W_fl, W_fr);
    prep_T_part <<<dim3(8,16), 256>>>(W_cl, W_cr, W_cout);
    prep_T_final<<<128, 256>>>();
    stage1_gemm <<<dim3(8,18), 256>>>();
    pair_gemm   <<<dim3(16,288), 384, SM_TOT>>>(mm, coords, out);
}

// round 11
// speedup vs baseline: 4.7582x; 1.1554x over previous
#include <cuda_runtime.h>
#include <cuda_fp16.h>
#include <cstdint>

#define BB 32
#define NR 36
#define DD 2048
#define CC 4
#define HH 512
#define HF 512
#define NROWS (BB*NR)   // 1152

// Scratch (static device globals)
__device__ __half g_mmh [NROWS*DD];   // mm in f16
__device__ __half g_Lh  [NROWS*HF];   // fl f16
__device__ __half g_Rh  [NROWS*HF];   // fr f16
__device__ __half g_Wt  [DD*HF];      // W_fout^T: [d][k]
__device__ __half g_WffT[1024*DD];    // [h][k] fused (W_fl|W_fr) transposed
__device__ __half g_T   [DD*16];      // coord tensor T[d][p*4+q] * 64
__device__ float  g_Tp  [16][DD*16];  // h-split partials for T

// ---------------- helpers ----------------
__device__ __forceinline__ uint32_t sm_u32(const void* p){
    uint32_t a;
    asm("{ .reg .u64 t; cvta.to.shared.u64 t, %1; cvt.u32.u64 %0, t; }" : "=r"(a) : "l"(p));
    return a;
}
__device__ __forceinline__ void mma16816(float c[4], const uint32_t a[4], const uint32_t b0, const uint32_t b1){
    asm volatile("mma.sync.aligned.m16n8k16.row.col.f32.f16.f16.f32 "
                 "{%0,%1,%2,%3}, {%4,%5,%6,%7}, {%8,%9}, {%0,%1,%2,%3};\n"
                 : "+f"(c[0]), "+f"(c[1]), "+f"(c[2]), "+f"(c[3])
                 : "r"(a[0]), "r"(a[1]), "r"(a[2]), "r"(a[3]), "r"(b0), "r"(b1));
}
__device__ __forceinline__ void ldm_x4(uint32_t d[4], uint32_t addr){
    asm volatile("ldmatrix.sync.aligned.m8n8.x4.shared.b16 {%0,%1,%2,%3}, [%4];"
                 : "=r"(d[0]), "=r"(d[1]), "=r"(d[2]), "=r"(d[3]) : "r"(addr));
}
__device__ __forceinline__ void cpa16(uint32_t dst, const void* src){
    asm volatile("cp.async.cg.shared.global [%0], [%1], 16;"
                 :: "r"(dst), "l"(__cvta_generic_to_global(src)) : "memory");
}
__device__ __forceinline__ void cpa_commit(){ asm volatile("cp.async.commit_group;" ::: "memory"); }
__device__ __forceinline__ void cpa_wait0(){ asm volatile("cp.async.wait_group 0;" ::: "memory"); }
__device__ __forceinline__ void cpa_wait1(){ asm volatile("cp.async.wait_group 1;" ::: "memory"); }
__device__ __forceinline__ unsigned f2mono(float v){
    unsigned b = __float_as_uint(v);
    return (b & 0x80000000u) ? ~b : (b | 0x80000000u);
}
__device__ __forceinline__ float mono2f(unsigned u){
    return (u & 0x80000000u) ? __uint_as_float(u ^ 0x80000000u) : __uint_as_float(~u);
}

// ---------------- fused prep kernel (all independent preps in one launch) ----------------
// blocks [0,1152): mmh   [1152,1664): w_out_t(32x16)   [1664,2688): w_in_t(16x64)   [2688,2816): T_part(8x16)
__global__ __launch_bounds__(256) void prep_all(const float* __restrict__ mm,
                                                const float* __restrict__ Wfout,
                                                const float* __restrict__ Wfl,
                                                const float* __restrict__ Wfr,
                                                const float* __restrict__ Wcl,
                                                const float* __restrict__ Wcr,
                                                const float* __restrict__ Wcout){
    __shared__ float ts[64][33];
    __shared__ float scl[4][32], scr[4][32];
    const int bid = blockIdx.x, tid = threadIdx.x;
    if (bid < 1152){
        int i = bid*256 + tid;
        const float4* s = reinterpret_cast<const float4*>(mm);
        float4 v0 = s[i*2], v1 = s[i*2+1];
        __half2* d = reinterpret_cast<__half2*>(g_mmh) + i*4;
        d[0] = __floats2half2_rn(v0.x, v0.y);
        d[1] = __floats2half2_rn(v0.z, v0.w);
        d[2] = __floats2half2_rn(v1.x, v1.y);
        d[3] = __floats2half2_rn(v1.z, v1.w);
    } else if (bid < 1664){
        int q = bid - 1152;
        int d0 = (q&31)*64, k0 = (q>>5)*32;
#pragma unroll
        for (int r=0;r<8;r++){
            int idx = tid + 256*r;
            int kk = idx>>6, dd = idx&63;
            ts[dd][kk] = Wfout[(size_t)(k0+kk)*DD + d0 + dd];
        }
        __syncthreads();
        __half2* Wt2 = reinterpret_cast<__half2*>(g_Wt);
#pragma unroll
        for (int r=0;r<4;r++){
            int idx = tid + 256*r;
            int dd = idx>>4, kk2 = idx&15;
            Wt2[(size_t)(d0+dd)*(HF/2) + (k0>>1) + kk2] =
                __floats2half2_rn(ts[dd][kk2*2], ts[dd][kk2*2+1]);
        }
    } else if (bid < 2688){
        int q = bid - 1664;
        int h0 = (q&15)*64, k0 = (q>>4)*32;
#pragma unroll
        for (int r=0;r<8;r++){
            int idx = tid + 256*r;
            int kk = idx>>6, hh = idx&63;
            int h = h0 + hh, k = k0 + kk;
            ts[hh][kk] = (h < HH) ? Wfl[(size_t)k*HH + h] : Wfr[(size_t)k*HH + h - HH];
        }
        __syncthreads();
        __half2* W2 = reinterpret_cast<__half2*>(g_WffT);
#pragma unroll
        for (int r=0;r<4;r++){
            int idx = tid + 256*r;
            int hh = idx>>4, kk2 = idx&15;
            W2[(size_t)(h0+hh)*(DD/2) + (k0>>1) + kk2] =
                __floats2half2_rn(ts[hh][kk2*2], ts[hh][kk2*2+1]);
        }
    } else {
        int q = bid - 2688;
        int dblk = q&7, hc = q>>3;
        int hbase = hc*32;
        if (tid < 128){
            int p = tid>>5, hh = tid&31;
            scl[p][hh] = Wcl[p*HH + hbase + hh];
            scr[p][hh] = Wcr[p*HH + hbase + hh];
        }
        __syncthreads();
        int d = dblk*256 + tid;
        float acc[16];
#pragma unroll
        for (int e=0;e<16;e++) acc[e]=0.f;
#pragma unroll
        for (int h0=0; h0<32; h0+=8){
            float wc[8];
#pragma unroll
            for (int u=0;u<8;u++) wc[u] = Wcout[(size_t)(hbase+h0+u)*DD + d];
#pragma unroll
            for (int u=0;u<8;u++){
                int hh = h0+u;
#pragma unroll
                for (int p=0;p<4;p++){
                    float a = scl[p][hh]*wc[u];
#pragma unroll
                    for (int r=0;r<4;r++) acc[p*4+r] = fmaf(a, scr[r][hh], acc[p*4+r]);
                }
            }
        }
#pragma unroll
        for (int e=0;e<16;e++) g_Tp[hc][d*16+e] = acc[e];
    }
}
__global__ void prep_T_final(){
    int i = blockIdx.x*256 + threadIdx.x;       // 32768 total
    float s = 0.f;
#pragma unroll
    for (int p=0;p<16;p++) s += g_Tp[p][i];
    g_T[i] = __float2half(s*64.0f);
}

// ---------------- stage 1: [fl|fr] = mm @ [W_fl|W_fr] (M=1152,K=2048,N=1024) ----------------
#define S1_A0 0
#define S1_A1 5120
#define S1_B0 10240
#define S1_B1 20480

__device__ __forceinline__ void s1_issue(uint32_t smb, int t, int sel, int tid, int m0, int n0){
    uint32_t Ab = smb + (sel ? S1_A1 : S1_A0);
    uint32_t Bb = smb + (sel ? S1_B1 : S1_B0);
    {
        int row = tid>>2, seg = tid&3;
        cpa16(Ab + row*80 + seg*16, (const char*)g_mmh + (size_t)(m0+row)*4096 + t*64 + seg*16);
    }
#pragma unroll
    for (int q=0;q<2;q++){
        int idx = tid + 256*q, row = idx>>2, seg = idx&3;
        cpa16(Bb + row*80 + seg*16, (const char*)g_WffT + (size_t)(n0+row)*4096 + t*64 + seg*16);
    }
    cpa_commit();
}

__global__ __launch_bounds__(256) void stage1_gemm(){
    __shared__ char sm[30720];
    uint32_t smb = sm_u32(sm);
    int tid = threadIdx.x, warp = tid>>5, lane = tid&31;
    int n0 = blockIdx.x*128, m0 = blockIdx.y*64;
    int wm = (warp&1)*32, wn = (warp>>1)*32;
    float acc[2][4][4];
#pragma unroll
    for (int a=0;a<2;a++) for (int b=0;b<4;b++) for (int c=0;c<4;c++) acc[a][b][c]=0.f;

    s1_issue(smb, 0, 0, tid, m0, n0);
    for (int t=0; t<64; t++){
        int sel = t&1;
        if (t<63){ s1_issue(smb, t+1, sel^1, tid, m0, n0); cpa_wait1(); }
        else cpa_wait0();
        __syncthreads();
        uint32_t Ab = smb + (sel ? S1_A1 : S1_A0);
        uint32_t Bb = smb + (sel ? S1_B1 : S1_B0);
#pragma unroll
        for (int ks=0; ks<2; ks++){
            uint32_t a[2][4], bfr[2][4];
#pragma unroll
            for (int mf=0;mf<2;mf++)
                ldm_x4(a[mf], Ab + (uint32_t)(wm+mf*16+(lane&15))*80 + ks*32 + ((lane>>4)<<4));
#pragma unroll
            for (int g=0;g<2;g++)
                ldm_x4(bfr[g], Bb + (uint32_t)(wn+g*16+(lane&15))*80 + ks*32 + ((lane>>4)<<4));
#pragma unroll
            for (int mf=0;mf<2;mf++)
#pragma unroll
                for (int g=0;g<2;g++)
#pragma unroll
                    for (int hi=0;hi<2;hi++)
                        mma16816(acc[mf][g*2+hi], a[mf], bfr[g][hi], bfr[g][hi+2]);
        }
        __syncthreads();
    }
#pragma unroll
    for (int mf=0;mf<2;mf++)
#pragma unroll
        for (int nf=0;nf<4;nf++){
            int g = nf>>1, hi = nf&1;
#pragma unroll
            for (int ci=0;ci<4;ci++){
                int row = m0 + wm + mf*16 + (lane>>2) + (ci>>1)*8;
                int col = n0 + wn + g*16 + hi*8 + (lane&3)*2 + (ci&1);
                __half v = __float2half(acc[mf][nf][ci]);
                if (col < HH) g_Lh[(size_t)row*HF + col]      = v;
                else          g_Rh[(size_t)row*HF + col - HH] = v;
            }
        }
}

// ---------------- pair GEMM: K=528, 1 barrier per chunk ----------------
// BM=144 pair-rows (4 i x 36 j), BN=128, 384 threads (3m x 4n warps)
#define SM_A0 0
#define SM_A1 11520
#define SM_B0 23040          // 3 x 10240
#define SM_R0 53760          // 3 x 2304
#define SM_L  60672
#define SM_CS 64768
#define SM_TOT 65408

__device__ __forceinline__ void issue_loads(uint32_t smb, int t, int bsel, int tid, int n0, int rbase){
    uint32_t Bb = smb + SM_B0 + bsel*10240;
    const char* bsrc = (const char*)g_Wt + (size_t)n0*1024 + (size_t)t*64;
    {
        int p = tid;
        cpa16(Bb + (p>>2)*80 + (p&3)*16, bsrc + (size_t)(p>>2)*1024 + (p&3)*16);
        if (tid < 128){
            int p2 = tid + 384;
            cpa16(Bb + (p2>>2)*80 + (p2&3)*16, bsrc + (size_t)(p2>>2)*1024 + (p2&3)*16);
        }
    }
    if (tid < 144){
        uint32_t rdst = smb + SM_R0 + bsel*2304 + (tid>>2)*64 + (tid&3)*16;
        const char* rsrc = (const char*)g_Rh + (size_t)(rbase + (tid>>2))*1024 + (size_t)t*64 + (tid&3)*16;
        cpa16(rdst, rsrc);
    }
    cpa_commit();
}

__device__ __forceinline__ void build_A(char* sm, int t, int asel, int rsel, int tid,
                                        const int* ggq, const int* jq){
    const __half2* Lh2 = (const __half2*)(sm + SM_L);
    const __half2* Rh2 = (const __half2*)(sm + SM_R0 + rsel*2304);
    char* Ab = sm + (asel ? SM_A1 : SM_A0);
    int k2 = tid & 15;
#pragma unroll
    for (int q=0;q<6;q++){
        int row = (tid>>4) + 24*q;
        __half2 l = Lh2[ggq[q]*256 + t*16 + k2];
        __half2 r = Rh2[jq[q]*16 + k2];
        *reinterpret_cast<__half2*>(Ab + row*80 + k2*4) = __hmul2(l, r);
    }
}

__global__ void __launch_bounds__(384,2) pair_gemm(const float* __restrict__ mm,
                                                   const float* __restrict__ coords,
                                                   float* __restrict__ out){
    extern __shared__ char sm[];
    const int tid = threadIdx.x, w = tid>>5, lane = tid&31;
    const int n0 = blockIdx.x*128;
    const int by = blockIdx.y, b = by/9, ig = by - b*9;
    const int lrow0 = b*NR + ig*4, rbase = b*NR;
    const uint32_t smb = sm_u32(sm);
    const int mrow0 = (w % 3)*48, ncol0 = (w / 3)*32;

    int ggq[6], jq[6];
#pragma unroll
    for (int q=0;q<6;q++){
        int row = (tid>>4) + 24*q;
        ggq[q] = row/36; jq[q] = row - 36*ggq[q];
    }

    {
        const uint4* src = reinterpret_cast<const uint4*>(g_Lh + (size_t)lrow0*HF);
        uint4* dst = reinterpret_cast<uint4*>(sm + SM_L);
        if (tid < 256) dst[tid] = src[tid];
        float* cs = reinterpret_cast<float*>(sm + SM_CS);
        if (tid < 16) cs[tid] = coords[(lrow0 + (tid>>2))*CC + (tid&3)];
        else if (tid < 160){ int e = tid-16; cs[tid] = coords[(rbase + (e>>2))*CC + (e&3)]; }
    }

    float acc[3][4][4];
#pragma unroll
    for (int m=0;m<3;m++) for (int n=0;n<4;n++) for (int c=0;c<4;c++) acc[m][n][c]=0.f;

    // prologue: chunks 0,1 in flight; build chunk 0
    issue_loads(smb, 0, 0, tid, n0, rbase);
    issue_loads(smb, 1, 1, tid, n0, rbase);
    cpa_wait0();
    __syncthreads();
    build_A(sm, 0, 0, 0, tid, ggq, jq);

    // single barrier per chunk: wait -> sync -> issue(t+2) -> build(t+1) -> compute(t)
    for (int t=0; t<16; t++){
        const int asel = t & 1;
        cpa_wait0();              // R/B for chunk t+1 arrived (issued >=1 full chunk ago)
        __syncthreads();          // visibility + separates compute(t-1) / build(t) from writers
        if (t < 14) issue_loads(smb, t+2, (t+2)%3, tid, n0, rbase);
        if (t < 15) build_A(sm, t+1, asel^1, (t+1)%3, tid, ggq, jq);

        const uint32_t ab = smb + (asel ? SM_A1 : SM_A0);
        const uint32_t bb = smb + SM_B0 + (t%3)*10240;
#pragma unroll
        for (int ks=0; ks<2; ks++){
            uint32_t a[3][4];
#pragma unroll
            for (int mf=0;mf<3;mf++)
                ldm_x4(a[mf], ab + (uint32_t)(mrow0 + mf*16 + (lane&15))*80 + ks*32 + ((lane>>4)<<4));
            uint32_t bf[2][4];
#pragma unroll
            for (int g=0; g<2; g++)
                ldm_x4(bf[g], bb + (uint32_t)(ncol0 + g*16 + (lane&15))*80 + ks*32 + ((lane>>4)<<4));
#pragma unroll
            for (int mf=0;mf<3;mf++)
#pragma unroll
                for (int nf=0;nf<4;nf++){
                    int g = nf>>1, hi = nf&1;
                    mma16816(acc[mf][nf], a[mf], bf[g][hi], bf[g][hi+2]);
                }
        }
    }
    __syncthreads();   // compute(15) done before coord chunk reuses A0/B0

    // ---- coord chunk (K=16): A = outer(c_i,c_j)/64, B = T tile ----
    {
        if (tid < 256){
            int row = tid>>1, seg = tid&1;
            cpa16(smb + SM_B0 + row*80 + seg*16,
                  (const char*)g_T + (size_t)(n0+row)*32 + seg*16);
        }
        cpa_commit();
        if (tid < 144){
            const float* cs = reinterpret_cast<const float*>(sm + SM_CS);
            int gg = tid/36, j = tid - gg*36;
            float ci[4], cj[4];
#pragma unroll
            for (int p=0;p<4;p++){ ci[p] = cs[gg*4+p]; cj[p] = cs[16 + j*4 + p]; }
            char* Ab = sm + SM_A0;
#pragma unroll
            for (int e2=0;e2<8;e2++){
                int p0 = (e2*2)>>2, q0 = (e2*2)&3, p1 = (e2*2+1)>>2, q1 = (e2*2+1)&3;
                *reinterpret_cast<__half2*>(Ab + tid*80 + e2*4) =
                    __floats2half2_rn(ci[p0]*cj[q0]*0.015625f, ci[p1]*cj[q1]*0.015625f);
            }
        }
        cpa_wait0();
        __syncthreads();
        uint32_t a[3][4], bf[2][4];
#pragma unroll
        for (int mf=0;mf<3;mf++)
            ldm_x4(a[mf], smb + SM_A0 + (uint32_t)(mrow0 + mf*16 + (lane&15))*80 + ((lane>>4)<<4));
#pragma unroll
        for (int g=0; g<2; g++)
            ldm_x4(bf[g], smb + SM_B0 + (uint32_t)(ncol0 + g*16 + (lane&15))*80 + ((lane>>4)<<4));
#pragma unroll
        for (int mf=0;mf<3;mf++)
#pragma unroll
            for (int nf=0;nf<4;nf++){
                int g = nf>>1, hi = nf&1;
                mma16816(acc[mf][nf], a[mf], bf[g][hi], bf[g][hi+2]);
            }
    }
    __syncthreads();

    // epilogue: register-merge per-thread rows with same group, then smem atomicMax
    unsigned* redu = reinterpret_cast<unsigned*>(sm);
    redu[tid] = 0u;
    if (tid < 128) redu[tid+384] = 0u;
    __syncthreads();
    int ggs[6];
#pragma unroll
    for (int s=0;s<6;s++){
        int row = mrow0 + (s>>1)*16 + (s&1)*8 + (lane>>2);
        ggs[s] = row/36;
    }
#pragma unroll
    for (int nf=0;nf<4;nf++)
#pragma unroll
        for (int cj=0;cj<2;cj++){
            int col = ncol0 + nf*8 + (lane&3)*2 + cj;
            float v = acc[0][nf][cj];       // s=0: mf=0,hi=0
            int g0 = ggs[0];
#pragma unroll
            for (int s=1;s<6;s++){
                float nv = acc[s>>1][nf][(s&1)*2+cj];
                if (ggs[s] == g0) v = fmaxf(v, nv);
                else { atomicMax(&redu[g0*128 + col], f2mono(v)); g0 = ggs[s]; v = nv; }
            }
            atomicMax(&redu[g0*128 + col], f2mono(v));
        }
    __syncthreads();
    for (int idx = tid; idx < 512; idx += 384){
        int gg = idx>>7, col = idx&127;
        float v = mono2f(redu[idx]);
        size_t o = (size_t)(lrow0 + gg)*DD + n0 + col;
        out[o] = v + mm[o];
    }
}

// ---------------- launch ----------------
extern "C" void kernel_launch(void* const* d_in, const int* in_sizes, int n_in,
                              void* d_out, int out_size){
    (void)in_sizes; (void)n_in; (void)out_size;
    const float* mm     = (const float*)d_in[0];
    const float* coords = (const float*)d_in[1];
    const float* W_cl   = (const float*)d_in[2];
    const float* W_cr   = (const float*)d_in[3];
    const float* W_cout = (const float*)d_in[4];
    const float* W_fl   = (const float*)d_in[5];
    const float* W_fr   = (const float*)d_in[6];
    const float* W_fout = (const float*)d_in[7];
    float* out = (float*)d_out;

    cudaFuncSetAttribute(pair_gemm, cudaFuncAttributeMaxDynamicSharedMemorySize, SM_TOT);

    prep_all    <<<2816, 256>>>(mm, W_fout, W_fl, W_fr, W_cl, W_cr, W_cout);
    prep_T_final<<<128, 256>>>();
    stage1_gemm <<<dim3(8,18), 256>>>();
    pair_gemm   <<<dim3(16,288), 384, SM_TOT>>>(mm, coords, out);
}

// round 13
// speedup vs baseline: 4.7816x; 1.0049x over previous
#include <cuda_runtime.h>
#include <cuda_fp16.h>
#include <cstdint>

#define BB 32
#define NR 36
#define DD 2048
#define CC 4
#define HH 512
#define HF 512
#define NROWS (BB*NR)   // 1152

// Scratch (static device globals)
__device__ __half g_mmh [NROWS*DD];   // mm in f16
__device__ __half g_Lh  [NROWS*HF];   // fl f16
__device__ __half g_Rh  [NROWS*HF];   // fr f16
__device__ __half g_Wt  [DD*HF];      // W_fout^T: [d][k]
__device__ __half g_WffT[1024*DD];    // [h][k] fused (W_fl|W_fr) transposed
__device__ __half g_T   [DD*16];      // coord tensor T[d][p*4+q] * 64
__device__ float  g_Tp  [16][DD*16];  // h-split partials for T
__device__ __half g_A   [288*144*HF]; // materialized pair products (42.3 MB)

// ---------------- helpers ----------------
__device__ __forceinline__ uint32_t sm_u32(const void* p){
    uint32_t a;
    asm("{ .reg .u64 t; cvta.to.shared.u64 t, %1; cvt.u32.u64 %0, t; }" : "=r"(a) : "l"(p));
    return a;
}
__device__ __forceinline__ void mma16816(float c[4], const uint32_t a[4], const uint32_t b0, const uint32_t b1){
    asm volatile("mma.sync.aligned.m16n8k16.row.col.f32.f16.f16.f32 "
                 "{%0,%1,%2,%3}, {%4,%5,%6,%7}, {%8,%9}, {%0,%1,%2,%3};\n"
                 : "+f"(c[0]), "+f"(c[1]), "+f"(c[2]), "+f"(c[3])
                 : "r"(a[0]), "r"(a[1]), "r"(a[2]), "r"(a[3]), "r"(b0), "r"(b1));
}
__device__ __forceinline__ void ldm_x4(uint32_t d[4], uint32_t addr){
    asm volatile("ldmatrix.sync.aligned.m8n8.x4.shared.b16 {%0,%1,%2,%3}, [%4];"
                 : "=r"(d[0]), "=r"(d[1]), "=r"(d[2]), "=r"(d[3]) : "r"(addr));
}
__device__ __forceinline__ void cpa16(uint32_t dst, const void* src){
    asm volatile("cp.async.cg.shared.global [%0], [%1], 16;"
                 :: "r"(dst), "l"(__cvta_generic_to_global(src)) : "memory");
}
__device__ __forceinline__ void cpa_commit(){ asm volatile("cp.async.commit_group;" ::: "memory"); }
__device__ __forceinline__ void cpa_wait0(){ asm volatile("cp.async.wait_group 0;" ::: "memory"); }
__device__ __forceinline__ void cpa_wait1(){ asm volatile("cp.async.wait_group 1;" ::: "memory"); }
__device__ __forceinline__ unsigned f2mono(float v){
    unsigned b = __float_as_uint(v);
    return (b & 0x80000000u) ? ~b : (b | 0x80000000u);
}
__device__ __forceinline__ float mono2f(unsigned u){
    return (u & 0x80000000u) ? __uint_as_float(u ^ 0x80000000u) : __uint_as_float(~u);
}

// ---------------- fused prep kernel ----------------
__global__ __launch_bounds__(256) void prep_all(const float* __restrict__ mm,
                                                const float* __restrict__ Wfout,
                                                const float* __restrict__ Wfl,
                                                const float* __restrict__ Wfr,
                                                const float* __restrict__ Wcl,
                                                const float* __restrict__ Wcr,
                                                const float* __restrict__ Wcout){
    __shared__ float ts[64][33];
    __shared__ float scl[4][32], scr[4][32];
    const int bid = blockIdx.x, tid = threadIdx.x;
    if (bid < 1152){
        int i = bid*256 + tid;
        const float4* s = reinterpret_cast<const float4*>(mm);
        float4 v0 = s[i*2], v1 = s[i*2+1];
        __half2* d = reinterpret_cast<__half2*>(g_mmh) + i*4;
        d[0] = __floats2half2_rn(v0.x, v0.y);
        d[1] = __floats2half2_rn(v0.z, v0.w);
        d[2] = __floats2half2_rn(v1.x, v1.y);
        d[3] = __floats2half2_rn(v1.z, v1.w);
    } else if (bid < 1664){
        int q = bid - 1152;
        int d0 = (q&31)*64, k0 = (q>>5)*32;
#pragma unroll
        for (int r=0;r<8;r++){
            int idx = tid + 256*r;
            int kk = idx>>6, dd = idx&63;
            ts[dd][kk] = Wfout[(size_t)(k0+kk)*DD + d0 + dd];
        }
        __syncthreads();
        __half2* Wt2 = reinterpret_cast<__half2*>(g_Wt);
#pragma unroll
        for (int r=0;r<4;r++){
            int idx = tid + 256*r;
            int dd = idx>>4, kk2 = idx&15;
            Wt2[(size_t)(d0+dd)*(HF/2) + (k0>>1) + kk2] =
                __floats2half2_rn(ts[dd][kk2*2], ts[dd][kk2*2+1]);
        }
    } else if (bid < 2688){
        int q = bid - 1664;
        int h0 = (q&15)*64, k0 = (q>>4)*32;
#pragma unroll
        for (int r=0;r<8;r++){
            int idx = tid + 256*r;
            int kk = idx>>6, hh = idx&63;
            int h = h0 + hh, k = k0 + kk;
            ts[hh][kk] = (h < HH) ? Wfl[(size_t)k*HH + h] : Wfr[(size_t)k*HH + h - HH];
        }
        __syncthreads();
        __half2* W2 = reinterpret_cast<__half2*>(g_WffT);
#pragma unroll
        for (int r=0;r<4;r++){
            int idx = tid + 256*r;
            int hh = idx>>4, kk2 = idx&15;
            W2[(size_t)(h0+hh)*(DD/2) + (k0>>1) + kk2] =
                __floats2half2_rn(ts[hh][kk2*2], ts[hh][kk2*2+1]);
        }
    } else {
        int q = bid - 2688;
        int dblk = q&7, hc = q>>3;
        int hbase = hc*32;
        if (tid < 128){
            int p = tid>>5, hh = tid&31;
            scl[p][hh] = Wcl[p*HH + hbase + hh];
            scr[p][hh] = Wcr[p*HH + hbase + hh];
        }
        __syncthreads();
        int d = dblk*256 + tid;
        float acc[16];
#pragma unroll
        for (int e=0;e<16;e++) acc[e]=0.f;
#pragma unroll
        for (int h0=0; h0<32; h0+=8){
            float wc[8];
#pragma unroll
            for (int u=0;u<8;u++) wc[u] = Wcout[(size_t)(hbase+h0+u)*DD + d];
#pragma unroll
            for (int u=0;u<8;u++){
                int hh = h0+u;
#pragma unroll
                for (int p=0;p<4;p++){
                    float a = scl[p][hh]*wc[u];
#pragma unroll
                    for (int r=0;r<4;r++) acc[p*4+r] = fmaf(a, scr[r][hh], acc[p*4+r]);
                }
            }
        }
#pragma unroll
        for (int e=0;e<16;e++) g_Tp[hc][d*16+e] = acc[e];
    }
}
__global__ void prep_T_final(){
    int i = blockIdx.x*256 + threadIdx.x;       // 32768 total
    float s = 0.f;
#pragma unroll
    for (int p=0;p<16;p++) s += g_Tp[p][i];
    g_T[i] = __float2half(s*64.0f);
}

// ---------------- stage 1 ----------------
#define S1_A0 0
#define S1_A1 5120
#define S1_B0 10240
#define S1_B1 20480

__device__ __forceinline__ void s1_issue(uint32_t smb, int t, int sel, int tid, int m0, int n0){
    uint32_t Ab = smb + (sel ? S1_A1 : S1_A0);
    uint32_t Bb = smb + (sel ? S1_B1 : S1_B0);
    {
        int row = tid>>2, seg = tid&3;
        cpa16(Ab + row*80 + seg*16, (const char*)g_mmh + (size_t)(m0+row)*4096 + t*64 + seg*16);
    }
#pragma unroll
    for (int q=0;q<2;q++){
        int idx = tid + 256*q, row = idx>>2, seg = idx&3;
        cpa16(Bb + row*80 + seg*16, (const char*)g_WffT + (size_t)(n0+row)*4096 + t*64 + seg*16);
    }
    cpa_commit();
}

__global__ __launch_bounds__(256) void stage1_gemm(){
    __shared__ char sm[30720];
    uint32_t smb = sm_u32(sm);
    int tid = threadIdx.x, warp = tid>>5, lane = tid&31;
    int n0 = blockIdx.x*128, m0 = blockIdx.y*64;
    int wm = (warp&1)*32, wn = (warp>>1)*32;
    float acc[2][4][4];
#pragma unroll
    for (int a=0;a<2;a++) for (int b=0;b<4;b++) for (int c=0;c<4;c++) acc[a][b][c]=0.f;

    s1_issue(smb, 0, 0, tid, m0, n0);
    for (int t=0; t<64; t++){
        int sel = t&1;
        if (t<63){ s1_issue(smb, t+1, sel^1, tid, m0, n0); cpa_wait1(); }
        else cpa_wait0();
        __syncthreads();
        uint32_t Ab = smb + (sel ? S1_A1 : S1_A0);
        uint32_t Bb = smb + (sel ? S1_B1 : S1_B0);
#pragma unroll
        for (int ks=0; ks<2; ks++){
            uint32_t a[2][4], bfr[2][4];
#pragma unroll
            for (int mf=0;mf<2;mf++)
                ldm_x4(a[mf], Ab + (uint32_t)(wm+mf*16+(lane&15))*80 + ks*32 + ((lane>>4)<<4));
#pragma unroll
            for (int g=0;g<2;g++)
                ldm_x4(bfr[g], Bb + (uint32_t)(wn+g*16+(lane&15))*80 + ks*32 + ((lane>>4)<<4));
#pragma unroll
            for (int mf=0;mf<2;mf++)
#pragma unroll
                for (int g=0;g<2;g++)
#pragma unroll
                    for (int hi=0;hi<2;hi++)
                        mma16816(acc[mf][g*2+hi], a[mf], bfr[g][hi], bfr[g][hi+2]);
        }
        __syncthreads();
    }
#pragma unroll
    for (int mf=0;mf<2;mf++)
#pragma unroll
        for (int nf=0;nf<4;nf++){
            int g = nf>>1, hi = nf&1;
#pragma unroll
            for (int ci=0;ci<4;ci++){
                int row = m0 + wm + mf*16 + (lane>>2) + (ci>>1)*8;
                int col = n0 + wn + g*16 + hi*8 + (lane&3)*2 + (ci&1);
                __half v = __float2half(acc[mf][nf][ci]);
                if (col < HH) g_Lh[(size_t)row*HF + col]      = v;
                else          g_Rh[(size_t)row*HF + col - HH] = v;
            }
        }
}

// ---------------- build_pairs: materialize A[pb][144][512] = L[i]*R[j] ----------------
__global__ __launch_bounds__(256) void build_pairs(){
    __shared__ __half Ls[4*HF];       // 256 uint4
    __shared__ __half Rs[36*HF];      // 2304 uint4
    const int pb = blockIdx.x, tid = threadIdx.x;
    const int b = pb/9, ig = pb - b*9;
    const int lrow0 = b*NR + ig*4, rbase = b*NR;
    {
        const uint4* lsrc = reinterpret_cast<const uint4*>(g_Lh + (size_t)lrow0*HF);
        reinterpret_cast<uint4*>(Ls)[tid] = lsrc[tid];            // 256 vecs, all threads
        const uint4* rsrc = reinterpret_cast<const uint4*>(g_Rh + (size_t)rbase*HF);
        uint4* rd = reinterpret_cast<uint4*>(Rs);
#pragma unroll
        for (int q=0;q<9;q++){                                    // 2304 vecs
            int i = tid + 256*q;
            rd[i] = rsrc[i];
        }
    }
    __syncthreads();
    uint4* dst = reinterpret_cast<uint4*>(g_A + (size_t)pb*144*HF);
    const uint4* L4 = reinterpret_cast<const uint4*>(Ls);
    const uint4* R4 = reinterpret_cast<const uint4*>(Rs);
#pragma unroll
    for (int v=0; v<36; v++){
        int idx = tid + 256*v;            // 0..9215
        int row = idx>>6, kv = idx&63;
        int gg = row/36, j = row - 36*gg;
        uint4 lv = L4[gg*64 + kv];
        uint4 rv = R4[j*64 + kv];
        __half2 a0 = __hmul2(*reinterpret_cast<__half2*>(&lv.x), *reinterpret_cast<__half2*>(&rv.x));
        __half2 a1 = __hmul2(*reinterpret_cast<__half2*>(&lv.y), *reinterpret_cast<__half2*>(&rv.y));
        __half2 a2 = __hmul2(*reinterpret_cast<__half2*>(&lv.z), *reinterpret_cast<__half2*>(&rv.z));
        __half2 a3 = __hmul2(*reinterpret_cast<__half2*>(&lv.w), *reinterpret_cast<__half2*>(&rv.w));
        uint4 ov;
        ov.x = *reinterpret_cast<uint32_t*>(&a0);
        ov.y = *reinterpret_cast<uint32_t*>(&a1);
        ov.z = *reinterpret_cast<uint32_t*>(&a2);
        ov.w = *reinterpret_cast<uint32_t*>(&a3);
        dst[idx] = ov;
    }
}

// ---------------- pair GEMM: pure cp.async->ldmatrix->mma, 1 barrier/chunk ----------------
#define PSM_A  0            // 3 x 11520
#define PSM_B  34560        // 3 x 10240
#define PSM_CS 65280        // 160 floats
#define PSM_TOT 65920

__device__ __forceinline__ void p_issue(uint32_t smb, int t, int buf, int tid, int n0, int pb){
    uint32_t Ab = smb + PSM_A + buf*11520;
    const char* asrc = (const char*)g_A + (size_t)pb*(144*HF*2) + (size_t)t*64;
    {
        int p = tid;                       // 576 vecs of 16B
        cpa16(Ab + (p>>2)*80 + (p&3)*16, asrc + (size_t)(p>>2)*1024 + (p&3)*16);
        if (tid < 192){
            int p2 = tid + 384;
            cpa16(Ab + (p2>>2)*80 + (p2&3)*16, asrc + (size_t)(p2>>2)*1024 + (p2&3)*16);
        }
    }
    uint32_t Bb = smb + PSM_B + buf*10240;
    const char* bsrc = (const char*)g_Wt + (size_t)n0*1024 + (size_t)t*64;
    {
        int p = tid;                       // 512 vecs
        cpa16(Bb + (p>>2)*80 + (p&3)*16, bsrc + (size_t)(p>>2)*1024 + (p&3)*16);
        if (tid < 128){
            int p2 = tid + 384;
            cpa16(Bb + (p2>>2)*80 + (p2&3)*16, bsrc + (size_t)(p2>>2)*1024 + (p2&3)*16);
        }
    }
    cpa_commit();
}

__global__ void __launch_bounds__(384,2) pair_gemm(const float* __restrict__ mm,
                                                   const float* __restrict__ coords,
                                                   float* __restrict__ out){
    extern __shared__ char sm[];
    const int tid = threadIdx.x, w = tid>>5, lane = tid&31;
    const int n0 = blockIdx.x*128;
    const int pb = blockIdx.y, b = pb/9, ig = pb - b*9;
    const int lrow0 = b*NR + ig*4, rbase = b*NR;
    const uint32_t smb = sm_u32(sm);
    const int mrow0 = (w % 3)*48, ncol0 = (w / 3)*32;

    {
        float* cs = reinterpret_cast<float*>(sm + PSM_CS);
        if (tid < 16) cs[tid] = coords[(lrow0 + (tid>>2))*CC + (tid&3)];
        else if (tid < 160){ int e = tid-16; cs[tid] = coords[(rbase + (e>>2))*CC + (e&3)]; }
    }

    float acc[3][4][4];
#pragma unroll
    for (int m=0;m<3;m++) for (int n=0;n<4;n++) for (int c=0;c<4;c++) acc[m][n][c]=0.f;

    p_issue(smb, 0, 0, tid, n0, pb);
    p_issue(smb, 1, 1, tid, n0, pb);

    for (int t=0; t<16; t++){
        if (t < 15) cpa_wait1(); else cpa_wait0();
        __syncthreads();
        if (t < 14) p_issue(smb, t+2, (t+2)%3, tid, n0, pb);

        const uint32_t ab = smb + PSM_A + (t%3)*11520;
        const uint32_t bb = smb + PSM_B + (t%3)*10240;
#pragma unroll
        for (int ks=0; ks<2; ks++){
            uint32_t a[3][4];
#pragma unroll
            for (int mf=0;mf<3;mf++)
                ldm_x4(a[mf], ab + (uint32_t)(mrow0 + mf*16 + (lane&15))*80 + ks*32 + ((lane>>4)<<4));
            uint32_t bf[2][4];
#pragma unroll
            for (int g=0; g<2; g++)
                ldm_x4(bf[g], bb + (uint32_t)(ncol0 + g*16 + (lane&15))*80 + ks*32 + ((lane>>4)<<4));
#pragma unroll
            for (int mf=0;mf<3;mf++)
#pragma unroll
                for (int nf=0;nf<4;nf++){
                    int g = nf>>1, hi = nf&1;
                    mma16816(acc[mf][nf], a[mf], bf[g][hi], bf[g][hi+2]);
                }
        }
    }
    __syncthreads();

    // ---- coord chunk (K=16): A = outer(c_i,c_j)/64, B = T tile ----
    {
        if (tid < 256){
            int row = tid>>1, seg = tid&1;
            cpa16(smb + PSM_B + row*80 + seg*16,
                  (const char*)g_T + (size_t)(n0+row)*32 + seg*16);
        }
        cpa_commit();
        if (tid < 144){
            const float* cs = reinterpret_cast<const float*>(sm + PSM_CS);
            int gg = tid/36, j = tid - gg*36;
            float ci[4], cj[4];
#pragma unroll
            for (int p=0;p<4;p++){ ci[p] = cs[gg*4+p]; cj[p] = cs[16 + j*4 + p]; }
            char* Ab = sm + PSM_A;
#pragma unroll
            for (int e2=0;e2<8;e2++){
                int p0 = (e2*2)>>2, q0 = (e2*2)&3, p1 = (e2*2+1)>>2, q1 = (e2*2+1)&3;
                *reinterpret_cast<__half2*>(Ab + tid*80 + e2*4) =
                    __floats2half2_rn(ci[p0]*cj[q0]*0.015625f, ci[p1]*cj[q1]*0.015625f);
            }
        }
        cpa_wait0();
        __syncthreads();
        uint32_t a[3][4], bf[2][4];
#pragma unroll
        for (int mf=0;mf<3;mf++)
            ldm_x4(a[mf], smb + PSM_A + (uint32_t)(mrow0 + mf*16 + (lane&15))*80 + ((lane>>4)<<4));
#pragma unroll
        for (int g=0; g<2; g++)
            ldm_x4(bf[g], smb + PSM_B + (uint32_t)(ncol0 + g*16 + (lane&15))*80 + ((lane>>4)<<4));
#pragma unroll
        for (int mf=0;mf<3;mf++)
#pragma unroll
            for (int nf=0;nf<4;nf++){
                int g = nf>>1, hi = nf&1;
                mma16816(acc[mf][nf], a[mf], bf[g][hi], bf[g][hi+2]);
            }
    }
    __syncthreads();

    // epilogue: register-merge same-group rows, then smem atomicMax
    unsigned* redu = reinterpret_cast<unsigned*>(sm);
    redu[tid] = 0u;
    if (tid < 128) redu[tid+384] = 0u;
    __syncthreads();
    int ggs[6];
#pragma unroll
    for (int s=0;s<6;s++){
        int row = mrow0 + (s>>1)*16 + (s&1)*8 + (lane>>2);
        ggs[s] = row/36;
    }
#pragma unroll
    for (int nf=0;nf<4;nf++)
#pragma unroll
        for (int cj=0;cj<2;cj++){
            int col = ncol0 + nf*8 + (lane&3)*2 + cj;
            float v = acc[0][nf][cj];
            int g0 = ggs[0];
#pragma unroll
            for (int s=1;s<6;s++){
                float nv = acc[s>>1][nf][(s&1)*2+cj];
                if (ggs[s] == g0) v = fmaxf(v, nv);
                else { atomicMax(&redu[g0*128 + col], f2mono(v)); g0 = ggs[s]; v = nv; }
            }
            atomicMax(&redu[g0*128 + col], f2mono(v));
        }
    __syncthreads();
    for (int idx = tid; idx < 512; idx += 384){
        int gg = idx>>7, col = idx&127;
        float v = mono2f(redu[idx]);
        size_t o = (size_t)(lrow0 + gg)*DD + n0 + col;
        out[o] = v + mm[o];
    }
}

// ---------------- launch ----------------
extern "C" void kernel_launch(void* const* d_in, const int* in_sizes, int n_in,
                              void* d_out, int out_size){
    (void)in_sizes; (void)n_in; (void)out_size;
    const float* mm     = (const float*)d_in[0];
    const float* coords = (const float*)d_in[1];
    const float* W_cl   = (const float*)d_in[2];
    const float* W_cr   = (const float*)d_in[3];
    const float* W_cout = (const float*)d_in[4];
    const float* W_fl   = (const float*)d_in[5];
    const float* W_fr   = (const float*)d_in[6];
    const float* W_fout = (const float*)d_in[7];
    float* out = (float*)d_out;

    cudaFuncSetAttribute(pair_gemm, cudaFuncAttributeMaxDynamicSharedMemorySize, PSM_TOT);

    prep_all    <<<2816, 256>>>(mm, W_fout, W_fl, W_fr, W_cl, W_cr, W_cout);
    prep_T_final<<<128, 256>>>();
    stage1_gemm <<<dim3(8,18), 256>>>();
    build_pairs <<<288, 256>>>();
    pair_gemm   <<<dim3(16,288), 384, PSM_TOT>>>(mm, coords, out);
}